// round 1
// baseline (speedup 1.0000x reference)
#include <cuda_runtime.h>
#include <math.h>

// ---------------- problem constants ----------------
#define NTOK 200704           // 4*16*56*56
#define BB 4
#define DD 16
#define HH 56
#define WW 56
#define CC 96

// ---------------- scratch (static device globals; allowed) ----------------
__device__ float g_xn  [NTOK*96];
__device__ float g_qkv [NTOK*288];
__device__ float g_attn[NTOK*96];
__device__ float g_x1  [NTOK*96];
__device__ float g_conv[NTOK*96];
__device__ float g_x2  [NTOK*96];
__device__ float g_h   [NTOK*384];
__device__ float g_part[4*4*112*2];
__device__ float g_stats[16*2];

// ---------------- LayerNorm over C=96 (1 warp / token, 8 tokens / block) ----
__global__ void ln_kernel(const float* __restrict__ x, const float* __restrict__ w,
                          const float* __restrict__ b, float* __restrict__ o) {
    int wid = threadIdx.x >> 5, lane = threadIdx.x & 31;
    long tok = (long)blockIdx.x * 8 + wid;
    const float* xr = x + tok * 96;
    float v0 = xr[lane], v1 = xr[lane + 32], v2 = xr[lane + 64];
    float s  = v0 + v1 + v2;
    float sq = v0*v0 + v1*v1 + v2*v2;
    #pragma unroll
    for (int off = 16; off; off >>= 1) {
        s  += __shfl_xor_sync(0xFFFFFFFFu, s,  off);
        sq += __shfl_xor_sync(0xFFFFFFFFu, sq, off);
    }
    float mu  = s * (1.f / 96.f);
    float var = sq * (1.f / 96.f) - mu * mu;
    float rs  = rsqrtf(var + 1e-5f);
    float* orow = o + tok * 96;
    orow[lane]      = (v0 - mu) * rs * w[lane]      + b[lane];
    orow[lane + 32] = (v1 - mu) * rs * w[lane + 32] + b[lane + 32];
    orow[lane + 64] = (v2 - mu) * rs * w[lane + 64] + b[lane + 64];
}

// ---------------- generic tiled GEMM: out[M,NO] = epi( A[M,K] @ W[NO,K]^T ) --
// BM=64 rows, BN=96 cols per block, K chunked by 48. 256 threads, 4x6 regs.
// PROLOG: 0 = plain A load, 1 = GroupNorm(4)+ReLU applied to A elements.
// EPILOG: 0 = store, 1 = +bias(optional) +resid, 2 = gelu(x+bias) exact.
template<int PROLOG, int EPILOG>
__global__ void gemm_k(const float* __restrict__ A, const float* __restrict__ W,
                       const float* __restrict__ bias, const float* __restrict__ resid,
                       float* __restrict__ out, int KTOT, int NOtot,
                       const float* __restrict__ gnstats,
                       const float* __restrict__ gnw, const float* __restrict__ gnb) {
    __shared__ float As[64][49];
    __shared__ float Ws[96][49];
    const int tid = threadIdx.x;
    const int ty = tid >> 4, tx = tid & 15;
    const long row0 = (long)blockIdx.x * 64;
    const int  col0 = blockIdx.y * 96;
    float acc[4][6];
    #pragma unroll
    for (int i = 0; i < 4; i++)
        #pragma unroll
        for (int j = 0; j < 6; j++) acc[i][j] = 0.f;

    for (int kc = 0; kc < KTOT; kc += 48) {
        for (int idx = tid; idx < 64 * 48; idx += 256) {
            int r = idx / 48, k = idx % 48;
            float v = A[(row0 + r) * KTOT + kc + k];
            if (PROLOG == 1) {
                int ci = kc + k;
                int gi = (int)((row0 + r) / 50176) * 4 + ci / 24;
                v = (v - gnstats[gi * 2]) * gnstats[gi * 2 + 1] * gnw[ci] + gnb[ci];
                v = fmaxf(v, 0.f);
            }
            As[r][k] = v;
        }
        for (int idx = tid; idx < 96 * 48; idx += 256) {
            int c2 = idx / 48, k = idx % 48;
            Ws[c2][k] = W[(long)(col0 + c2) * KTOT + kc + k];
        }
        __syncthreads();
        #pragma unroll 4
        for (int k = 0; k < 48; ++k) {
            float a[4], wv[6];
            #pragma unroll
            for (int i = 0; i < 4; i++) a[i] = As[ty * 4 + i][k];
            #pragma unroll
            for (int j = 0; j < 6; j++) wv[j] = Ws[tx * 6 + j][k];
            #pragma unroll
            for (int i = 0; i < 4; i++)
                #pragma unroll
                for (int j = 0; j < 6; j++) acc[i][j] += a[i] * wv[j];
        }
        __syncthreads();
    }
    #pragma unroll
    for (int i = 0; i < 4; i++) {
        long row = row0 + ty * 4 + i;
        #pragma unroll
        for (int j = 0; j < 6; j++) {
            int col = col0 + tx * 6 + j;
            float v = acc[i][j];
            if (EPILOG == 1) {
                if (bias) v += bias[col];
                v += resid[row * NOtot + col];
            } else if (EPILOG == 2) {
                v += bias[col];
                v = 0.5f * v * (1.f + erff(v * 0.70710678118654752f));
            }
            out[row * NOtot + col] = v;
        }
    }
}

// ---------------- multi-dilate local attention ------------------------------
// One block per (window, dilation). 98 tokens/window, 32 ch/dilation, 2 heads.
// Softmax over 9 slots: 6 structural zeros contribute exp(0); out-of-range
// neighbors give logit 0 (zero-padded k) and zero v — matches reference.
__global__ void attn_kernel(const float* __restrict__ qkv, float* __restrict__ outb) {
    __shared__ int   toks[98];
    __shared__ float ks[98 * 32];
    __shared__ float vs[98 * 32];
    int win = blockIdx.x;
    int dil = blockIdx.y + 1;          // dilations 1,2,3
    int choff = blockIdx.y * 32;
    int tid = threadIdx.x;
    if (tid < 98) {
        int b  = win >> 9;
        int dq = (win >> 6) & 7;
        int hq = (win >> 3) & 7;
        int wq = win & 7;
        int wd = tid / 49, rem = tid % 49;
        int wh = rem / 7, ww = rem % 7;
        int d = dq * 2 + wd, h = hq * 7 + wh, w = wq * 7 + ww;
        toks[tid] = ((b * 16 + d) * 56 + h) * 56 + w;
    }
    __syncthreads();
    for (int idx = tid; idx < 98 * 32; idx += 224) {
        int n = idx >> 5, c2 = idx & 31;
        long base = (long)toks[n] * 288 + choff + c2;
        ks[idx] = qkv[base + 96];
        vs[idx] = qkv[base + 192];
    }
    __syncthreads();
    if (tid < 196) {
        int n = tid >> 1, head = tid & 1;
        long qbase = (long)toks[n] * 288 + choff + head * 16;
        float q[16];
        #pragma unroll
        for (int c = 0; c < 16; c++) q[c] = qkv[qbase + c];
        float lr[3]; int mm[3];
        #pragma unroll
        for (int j = 0; j < 3; j++) {
            int m = n + (j - 1) * dil;
            mm[j] = m;
            float s = 0.f;
            if (m >= 0 && m < 98) {
                const float* kr = &ks[m * 32 + head * 16];
                #pragma unroll
                for (int c = 0; c < 16; c++) s += q[c] * kr[c];
            }
            lr[j] = s * 0.25f;   // head_dim^-0.5 = 16^-0.5
        }
        float mx = fmaxf(0.f, fmaxf(lr[0], fmaxf(lr[1], lr[2])));
        float e[3];
        e[0] = expf(lr[0] - mx); e[1] = expf(lr[1] - mx); e[2] = expf(lr[2] - mx);
        float denom = 6.f * expf(-mx) + e[0] + e[1] + e[2];
        float o[16];
        #pragma unroll
        for (int c = 0; c < 16; c++) o[c] = 0.f;
        #pragma unroll
        for (int j = 0; j < 3; j++) {
            int m = mm[j];
            if (m >= 0 && m < 98) {
                float a = e[j] / denom;
                const float* vr = &vs[m * 32 + head * 16];
                #pragma unroll
                for (int c = 0; c < 16; c++) o[c] += a * vr[c];
            }
        }
        long obase = (long)toks[n] * 96 + choff + head * 16;
        #pragma unroll
        for (int c = 0; c < 16; c++) outb[obase + c] = o[c];
    }
}

// ---------------- grouped 3x3x3 conv (groups=3), channels-last --------------
// Block: one (b, d, 8x8 hw tile, group). Weights for the group resident in
// smem as [tap][ci][co] (conflict-free co-contiguous); input staged per kd
// plane. Thread = (co, h-row), 8-wide w strip in registers.
__global__ void conv3_kernel(const float* __restrict__ x, const float* __restrict__ cw,
                             float* __restrict__ o) {
    extern __shared__ float sm[];
    float* w_s  = sm;            // 27*32*32 = 27648
    float* in_s = sm + 27648;    // 10*10*32 = 3200
    int bid = blockIdx.x;
    int g = bid % 3; int t2 = bid / 3;
    int tw = t2 % 7; int th = (t2 / 7) % 7; int d = (t2 / 49) % 16; int b = t2 / (49 * 16);
    int tid = threadIdx.x;
    int co_l = tid & 31, hrow = tid >> 5;

    for (int idx = tid; idx < 27648; idx += 256) {
        float v = cw[g * 27648 + idx];
        int col2 = idx / 864, rem = idx % 864;
        int ci = rem / 27, tap = rem % 27;
        w_s[(tap * 32 + ci) * 32 + col2] = v;
    }
    float acc[8];
    #pragma unroll
    for (int i = 0; i < 8; i++) acc[i] = 0.f;
    int h0 = th * 8, w0 = tw * 8;

    for (int kd = 0; kd < 3; kd++) {
        int dd = d - 1 + kd;
        __syncthreads();   // weights ready (kd=0) / previous-plane readers done
        for (int idx = tid; idx < 3200; idx += 256) {
            int hh = idx / 320; int rem = idx % 320; int ww2 = rem >> 5; int ci = rem & 31;
            int ih = h0 - 1 + hh, iw = w0 - 1 + ww2;
            float v = 0.f;
            if (dd >= 0 && dd < 16 && ih >= 0 && ih < 56 && iw >= 0 && iw < 56)
                v = x[((long)((b * 16 + dd) * 56 + ih) * 56 + iw) * 96 + g * 32 + ci];
            in_s[idx] = v;
        }
        __syncthreads();
        #pragma unroll
        for (int kh = 0; kh < 3; kh++) {
            const float* inrow = &in_s[(hrow + kh) * 320];
            int tb = (kd * 3 + kh) * 3;
            for (int ci = 0; ci < 32; ci++) {
                float wr0 = w_s[((tb + 0) * 32 + ci) * 32 + co_l];
                float wr1 = w_s[((tb + 1) * 32 + ci) * 32 + co_l];
                float wr2 = w_s[((tb + 2) * 32 + ci) * 32 + co_l];
                float rv[10];
                #pragma unroll
                for (int q2 = 0; q2 < 10; q2++) rv[q2] = inrow[q2 * 32 + ci];
                #pragma unroll
                for (int ww2 = 0; ww2 < 8; ww2++)
                    acc[ww2] += rv[ww2] * wr0 + rv[ww2 + 1] * wr1 + rv[ww2 + 2] * wr2;
            }
        }
    }
    long obase = ((long)((b * 16 + d) * 56 + h0 + hrow) * 56 + w0) * 96 + g * 32 + co_l;
    #pragma unroll
    for (int ww2 = 0; ww2 < 8; ww2++) o[obase + ww2 * 96] = acc[ww2];
}

// ---------------- GroupNorm(4) stats: deterministic 2-stage reduction -------
__global__ void gnred_kernel(const float* __restrict__ cv, float* __restrict__ part) {
    __shared__ float ss[256], sqv[256];
    int bg = blockIdx.x / 112, chunk = blockIdx.x % 112;
    int b = bg >> 2, gg = bg & 3;
    long vox0 = (long)b * 50176 + chunk * 448;
    float s = 0.f, q2 = 0.f;
    for (int idx = threadIdx.x; idx < 448 * 24; idx += 256) {
        int v = idx / 24, c2 = idx % 24;
        float val = cv[(vox0 + v) * 96 + gg * 24 + c2];
        s += val; q2 += val * val;
    }
    ss[threadIdx.x] = s; sqv[threadIdx.x] = q2;
    __syncthreads();
    for (int off = 128; off; off >>= 1) {
        if (threadIdx.x < off) {
            ss[threadIdx.x]  += ss[threadIdx.x + off];
            sqv[threadIdx.x] += sqv[threadIdx.x + off];
        }
        __syncthreads();
    }
    if (threadIdx.x == 0) {
        part[blockIdx.x * 2]     = ss[0];
        part[blockIdx.x * 2 + 1] = sqv[0];
    }
}

__global__ void gncomb_kernel(const float* __restrict__ part, float* __restrict__ stats) {
    int t = threadIdx.x;
    if (t < 16) {
        double s = 0.0, q2 = 0.0;
        for (int i = 0; i < 112; i++) {
            s  += (double)part[(t * 112 + i) * 2];
            q2 += (double)part[(t * 112 + i) * 2 + 1];
        }
        double N = 24.0 * 50176.0;
        double mu  = s / N;
        double var = q2 / N - mu * mu;
        stats[t * 2]     = (float)mu;
        stats[t * 2 + 1] = (float)(1.0 / sqrt(var + 1e-5));
    }
}

// ---------------- driver -----------------------------------------------------
extern "C" void kernel_launch(void* const* d_in, const int* in_sizes, int n_in,
                              void* d_out, int out_size) {
    const float* x       = (const float*)d_in[0];
    const float* n1w     = (const float*)d_in[1];
    const float* n1b     = (const float*)d_in[2];
    const float* qkv_w   = (const float*)d_in[3];
    const float* proj_w  = (const float*)d_in[4];
    const float* proj_b  = (const float*)d_in[5];
    const float* conv3_w = (const float*)d_in[6];
    const float* gn_w    = (const float*)d_in[7];
    const float* gn_b    = (const float*)d_in[8];
    const float* convp_w = (const float*)d_in[9];
    const float* n2w     = (const float*)d_in[10];
    const float* n2b     = (const float*)d_in[11];
    const float* fc1_w   = (const float*)d_in[12];
    const float* fc1_b   = (const float*)d_in[13];
    const float* fc2_w   = (const float*)d_in[14];
    const float* fc2_b   = (const float*)d_in[15];
    float* out = (float*)d_out;

    float *p_xn, *p_qkv, *p_attn, *p_x1, *p_conv, *p_x2, *p_h, *p_part, *p_stats;
    cudaGetSymbolAddress((void**)&p_xn,   g_xn);
    cudaGetSymbolAddress((void**)&p_qkv,  g_qkv);
    cudaGetSymbolAddress((void**)&p_attn, g_attn);
    cudaGetSymbolAddress((void**)&p_x1,   g_x1);
    cudaGetSymbolAddress((void**)&p_conv, g_conv);
    cudaGetSymbolAddress((void**)&p_x2,   g_x2);
    cudaGetSymbolAddress((void**)&p_h,    g_h);
    cudaGetSymbolAddress((void**)&p_part, g_part);
    cudaGetSymbolAddress((void**)&p_stats,g_stats);

    cudaFuncSetAttribute(conv3_kernel, cudaFuncAttributeMaxDynamicSharedMemorySize, 123392);

    // 1) LN1
    ln_kernel<<<25088, 256>>>(x, n1w, n1b, p_xn);
    // 2) qkv = xn @ qkv_w^T  (no bias)
    gemm_k<0,0><<<dim3(3136, 3), 256>>>(p_xn, qkv_w, nullptr, nullptr, p_qkv,
                                        96, 288, nullptr, nullptr, nullptr);
    // 3) multi-dilate local attention
    attn_kernel<<<dim3(2048, 3), 224>>>(p_qkv, p_attn);
    // 4) x1 = x + attn @ proj_w^T + proj_b
    gemm_k<0,1><<<dim3(3136, 1), 256>>>(p_attn, proj_w, proj_b, x, p_x1,
                                        96, 96, nullptr, nullptr, nullptr);
    // 5) grouped 3x3x3 conv
    conv3_kernel<<<9408, 256, 123392>>>(p_x1, conv3_w, p_conv);
    // 6) GroupNorm stats (deterministic)
    gnred_kernel<<<1792, 256>>>(p_conv, p_part);
    gncomb_kernel<<<1, 16>>>(p_part, p_stats);
    // 7) x2 = x1 + relu(GN(conv)) @ convp_w^T   (GN+ReLU in GEMM prologue)
    gemm_k<1,1><<<dim3(3136, 1), 256>>>(p_conv, convp_w, nullptr, p_x1, p_x2,
                                        96, 96, p_stats, gn_w, gn_b);
    // 8) LN2 (reuse g_xn)
    ln_kernel<<<25088, 256>>>(p_x2, n2w, n2b, p_xn);
    // 9) h = gelu(xn2 @ fc1_w^T + fc1_b)
    gemm_k<0,2><<<dim3(3136, 4), 256>>>(p_xn, fc1_w, fc1_b, nullptr, p_h,
                                        96, 384, nullptr, nullptr, nullptr);
    // 10) out = x2 + h @ fc2_w^T + fc2_b
    gemm_k<0,1><<<dim3(3136, 1), 256>>>(p_h, fc2_w, fc2_b, p_x2, out,
                                        384, 96, nullptr, nullptr, nullptr);
}

// round 4
// speedup vs baseline: 1.5533x; 1.5533x over previous
#include <cuda_runtime.h>
#include <cuda_bf16.h>
#include <math.h>
#include <cstdint>

// ---------------- problem constants ----------------
#define NTOK 200704           // 4*16*56*56

// ---------------- scratch (static device globals; allowed) ----------------
__device__ float g_qkv [NTOK*288];
__device__ float g_attn[NTOK*96];
__device__ float g_x1  [NTOK*96];
__device__ float g_conv[NTOK*96];
__device__ float g_x2  [NTOK*96];
__device__ float g_part[4*4*112*2];
__device__ float g_stats[16*2];
__device__ __nv_bfloat16 g_xnb [NTOK*96];
__device__ __nv_bfloat16 g_attb[NTOK*96];
__device__ __nv_bfloat16 g_cbf [NTOK*96];
__device__ __nv_bfloat16 g_hbf [NTOK*384];
__device__ __nv_bfloat16 g_wq  [288*96];
__device__ __nv_bfloat16 g_wp  [96*96];
__device__ __nv_bfloat16 g_wc  [96*96];
__device__ __nv_bfloat16 g_w1  [384*96];
__device__ __nv_bfloat16 g_w2  [96*384];

// ---------------- warp-MMA helpers (arch-agnostic PTX, sm_80+) --------------
__device__ __forceinline__ uint32_t smem_u32(const void* p) {
    uint32_t a;
    asm("{ .reg .u64 t; cvta.to.shared.u64 t, %1; cvt.u32.u64 %0, t; }" : "=r"(a) : "l"(p));
    return a;
}
__device__ __forceinline__ void ldsm_x4(uint32_t* r, uint32_t addr) {
    asm volatile("ldmatrix.sync.aligned.m8n8.x4.shared.b16 {%0,%1,%2,%3}, [%4];"
        : "=r"(r[0]), "=r"(r[1]), "=r"(r[2]), "=r"(r[3]) : "r"(addr));
}
__device__ __forceinline__ void mma16816(float* d, const uint32_t* a, const uint32_t* b) {
    asm volatile(
        "mma.sync.aligned.m16n8k16.row.col.f32.bf16.bf16.f32 "
        "{%0,%1,%2,%3}, {%4,%5,%6,%7}, {%8,%9}, {%0,%1,%2,%3};"
        : "+f"(d[0]), "+f"(d[1]), "+f"(d[2]), "+f"(d[3])
        : "r"(a[0]), "r"(a[1]), "r"(a[2]), "r"(a[3]), "r"(b[0]), "r"(b[1]));
}

// ---------------- tensor-core GEMM: out[M,NO] = epi( A[M,K] @ W[NO,K]^T ) ----
// CTA tile 128x96, 8 warps (4M x 2N), warp tile 32x48. K chunked by 96 in smem.
// EPI: 0 = store fp32; 1 = +bias(opt) +resid, fp32; 2 = gelu(x+bias) -> bf16.
template<int KT, int EPI>
__global__ __launch_bounds__(256)
void tgemm(const __nv_bfloat16* __restrict__ A, const __nv_bfloat16* __restrict__ W,
           const float* __restrict__ bias, const float* __restrict__ resid,
           void* __restrict__ outv, int NOtot) {
    constexpr int KC = 96;
    constexpr int PITCH = KC + 8;     // 104 bf16 = 208 B row pitch (conflict-free)
    __shared__ __nv_bfloat16 As[128 * PITCH];
    __shared__ __nv_bfloat16 Bs[96 * PITCH];
    const int tid = threadIdx.x;
    const int wid = tid >> 5, lane = tid & 31;
    const int warpM = wid & 3, warpN = wid >> 2;
    const long row0 = (long)blockIdx.x * 128;
    const int  col0 = blockIdx.y * 96;

    float acc[2][6][4];
    #pragma unroll
    for (int i = 0; i < 2; i++)
        #pragma unroll
        for (int j = 0; j < 6; j++)
            #pragma unroll
            for (int q = 0; q < 4; q++) acc[i][j][q] = 0.f;

    const uint32_t smA = smem_u32(As), smB = smem_u32(Bs);
    const int t8 = lane & 7, tq = lane >> 3;      // tq in 0..3
    // A ldmatrix (non-trans): tiles {m0..7,k0},{m8..15,k0},{m0..7,k8},{m8..15,k8}
    const int rowA_base = warpM * 32 + t8 + (tq & 1) * 8;
    const int koffA = (tq >> 1) * 8;
    uint32_t offA[2];
    #pragma unroll
    for (int mf = 0; mf < 2; mf++)
        offA[mf] = smA + (uint32_t)(((rowA_base + mf * 16) * PITCH + koffA) * 2);
    // B ldmatrix (non-trans): tiles {n0..7,k0},{n0..7,k8},{n8..15,k0},{n8..15,k8}
    const int rowB_base = warpN * 48 + t8 + (tq >> 1) * 8;
    const int koffB = (tq & 1) * 8;
    uint32_t offB[3];
    #pragma unroll
    for (int np = 0; np < 3; np++)
        offB[np] = smB + (uint32_t)(((rowB_base + np * 16) * PITCH + koffB) * 2);

    for (int kc = 0; kc < KT; kc += KC) {
        if (kc) __syncthreads();
        // stage A tile (128 x 96) vectorized
        #pragma unroll
        for (int it = 0; it < 6; it++) {
            int idx = tid + it * 256;              // 128*12 = 1536
            int r = idx / 12, k = (idx % 12) * 8;
            uint4 v = *(const uint4*)(A + (row0 + r) * KT + kc + k);
            *(uint4*)(&As[r * PITCH + k]) = v;
        }
        // stage B tile (96 x 96)
        for (int idx = tid; idx < 96 * 12; idx += 256) {
            int n = idx / 12, k = (idx % 12) * 8;
            uint4 v = *(const uint4*)(W + (long)(col0 + n) * KT + kc + k);
            *(uint4*)(&Bs[n * PITCH + k]) = v;
        }
        __syncthreads();
        #pragma unroll
        for (int ks = 0; ks < 6; ks++) {
            uint32_t af[2][4], bf[3][4];
            ldsm_x4(af[0], offA[0] + ks * 32);
            ldsm_x4(af[1], offA[1] + ks * 32);
            ldsm_x4(bf[0], offB[0] + ks * 32);
            ldsm_x4(bf[1], offB[1] + ks * 32);
            ldsm_x4(bf[2], offB[2] + ks * 32);
            #pragma unroll
            for (int mf = 0; mf < 2; mf++)
                #pragma unroll
                for (int np = 0; np < 3; np++) {
                    mma16816(acc[mf][np * 2 + 0], af[mf], &bf[np][0]);
                    mma16816(acc[mf][np * 2 + 1], af[mf], &bf[np][2]);
                }
        }
    }

    // epilogue: thread (g, tig) owns rows {g, g+8}, cols {2tig, 2tig+1} of each frag
    const int g = lane >> 2, tig = lane & 3;
    #pragma unroll
    for (int mf = 0; mf < 2; mf++) {
        #pragma unroll
        for (int nf = 0; nf < 6; nf++) {
            int col = col0 + warpN * 48 + nf * 8 + tig * 2;
            #pragma unroll
            for (int h = 0; h < 2; h++) {          // h=0: row g ; h=1: row g+8
                long row = row0 + warpM * 32 + mf * 16 + g + h * 8;
                float v0 = acc[mf][nf][h * 2 + 0];
                float v1 = acc[mf][nf][h * 2 + 1];
                if (EPI == 0) {
                    *(float2*)((float*)outv + row * NOtot + col) = make_float2(v0, v1);
                } else if (EPI == 1) {
                    if (bias) { v0 += bias[col]; v1 += bias[col + 1]; }
                    const float2 rr = *(const float2*)(resid + row * NOtot + col);
                    v0 += rr.x; v1 += rr.y;
                    *(float2*)((float*)outv + row * NOtot + col) = make_float2(v0, v1);
                } else {
                    v0 += bias[col]; v1 += bias[col + 1];
                    v0 = 0.5f * v0 * (1.f + erff(v0 * 0.70710678118654752f));
                    v1 = 0.5f * v1 * (1.f + erff(v1 * 0.70710678118654752f));
                    __nv_bfloat162 p = __floats2bfloat162_rn(v0, v1);
                    *(__nv_bfloat162*)((__nv_bfloat16*)outv + row * NOtot + col) = p;
                }
            }
        }
    }
}

// ---------------- LayerNorm over C=96 -> bf16 (1 warp / token) --------------
__global__ void ln_bf_kernel(const float* __restrict__ x, const float* __restrict__ w,
                             const float* __restrict__ b, __nv_bfloat16* __restrict__ o) {
    int wid = threadIdx.x >> 5, lane = threadIdx.x & 31;
    long tok = (long)blockIdx.x * 8 + wid;
    const float* xr = x + tok * 96;
    float v0 = xr[lane], v1 = xr[lane + 32], v2 = xr[lane + 64];
    float s  = v0 + v1 + v2;
    float sq = v0*v0 + v1*v1 + v2*v2;
    #pragma unroll
    for (int off = 16; off; off >>= 1) {
        s  += __shfl_xor_sync(0xFFFFFFFFu, s,  off);
        sq += __shfl_xor_sync(0xFFFFFFFFu, sq, off);
    }
    float mu  = s * (1.f / 96.f);
    float var = sq * (1.f / 96.f) - mu * mu;
    float rs  = rsqrtf(var + 1e-5f);
    __nv_bfloat16* orow = o + tok * 96;
    orow[lane]      = __float2bfloat16((v0 - mu) * rs * w[lane]      + b[lane]);
    orow[lane + 32] = __float2bfloat16((v1 - mu) * rs * w[lane + 32] + b[lane + 32]);
    orow[lane + 64] = __float2bfloat16((v2 - mu) * rs * w[lane + 64] + b[lane + 64]);
}

// ---------------- fp32 -> bf16 ----------------------------------------------
__global__ void f2bf_kernel(const float* __restrict__ a, __nv_bfloat16* __restrict__ o, int n) {
    int i = blockIdx.x * 256 + threadIdx.x;
    if (i < n) o[i] = __float2bfloat16(a[i]);
}

// ---------------- GN(4) + ReLU -> bf16 --------------------------------------
__global__ void gnrelu_bf_kernel(const float* __restrict__ cv, const float* __restrict__ stats,
                                 const float* __restrict__ gnw, const float* __restrict__ gnb,
                                 __nv_bfloat16* __restrict__ o) {
    long i = (long)blockIdx.x * 256 + threadIdx.x;
    long vox = i / 96; int c = (int)(i % 96);
    int gi = (int)(vox / 50176) * 4 + c / 24;
    float v = cv[i];
    v = (v - stats[gi * 2]) * stats[gi * 2 + 1] * gnw[c] + gnb[c];
    o[i] = __float2bfloat16(fmaxf(v, 0.f));
}

// ---------------- multi-dilate local attention (fp32) -----------------------
__global__ void attn_kernel(const float* __restrict__ qkv, float* __restrict__ outb) {
    __shared__ int   toks[98];
    __shared__ float ks[98 * 32];
    __shared__ float vs[98 * 32];
    int win = blockIdx.x;
    int dil = blockIdx.y + 1;
    int choff = blockIdx.y * 32;
    int tid = threadIdx.x;
    if (tid < 98) {
        int b  = win >> 9;
        int dq = (win >> 6) & 7;
        int hq = (win >> 3) & 7;
        int wq = win & 7;
        int wd = tid / 49, rem = tid % 49;
        int wh = rem / 7, ww = rem % 7;
        int d = dq * 2 + wd, h = hq * 7 + wh, w = wq * 7 + ww;
        toks[tid] = ((b * 16 + d) * 56 + h) * 56 + w;
    }
    __syncthreads();
    for (int idx = tid; idx < 98 * 32; idx += 224) {
        int n = idx >> 5, c2 = idx & 31;
        long base = (long)toks[n] * 288 + choff + c2;
        ks[idx] = qkv[base + 96];
        vs[idx] = qkv[base + 192];
    }
    __syncthreads();
    if (tid < 196) {
        int n = tid >> 1, head = tid & 1;
        long qbase = (long)toks[n] * 288 + choff + head * 16;
        float q[16];
        #pragma unroll
        for (int c = 0; c < 16; c++) q[c] = qkv[qbase + c];
        float lr[3]; int mm[3];
        #pragma unroll
        for (int j = 0; j < 3; j++) {
            int m = n + (j - 1) * dil;
            mm[j] = m;
            float s = 0.f;
            if (m >= 0 && m < 98) {
                const float* kr = &ks[m * 32 + head * 16];
                #pragma unroll
                for (int c = 0; c < 16; c++) s += q[c] * kr[c];
            }
            lr[j] = s * 0.25f;
        }
        float mx = fmaxf(0.f, fmaxf(lr[0], fmaxf(lr[1], lr[2])));
        float e[3];
        e[0] = expf(lr[0] - mx); e[1] = expf(lr[1] - mx); e[2] = expf(lr[2] - mx);
        float denom = 6.f * expf(-mx) + e[0] + e[1] + e[2];
        float o[16];
        #pragma unroll
        for (int c = 0; c < 16; c++) o[c] = 0.f;
        #pragma unroll
        for (int j = 0; j < 3; j++) {
            int m = mm[j];
            if (m >= 0 && m < 98) {
                float a = e[j] / denom;
                const float* vr = &vs[m * 32 + head * 16];
                #pragma unroll
                for (int c = 0; c < 16; c++) o[c] += a * vr[c];
            }
        }
        long obase = (long)toks[n] * 96 + choff + head * 16;
        #pragma unroll
        for (int c = 0; c < 16; c++) outb[obase + c] = o[c];
    }
}

// ---------------- grouped 3x3x3 conv (groups=3), fp32 -----------------------
__global__ void conv3_kernel(const float* __restrict__ x, const float* __restrict__ cw,
                             float* __restrict__ o) {
    extern __shared__ float smf[];
    float* w_s  = smf;            // 27*32*32
    float* in_s = smf + 27648;    // 10*10*32
    int bid = blockIdx.x;
    int g = bid % 3; int t2 = bid / 3;
    int tw = t2 % 7; int th = (t2 / 7) % 7; int d = (t2 / 49) % 16; int b = t2 / (49 * 16);
    int tid = threadIdx.x;
    int co_l = tid & 31, hrow = tid >> 5;

    for (int idx = tid; idx < 27648; idx += 256) {
        float v = cw[g * 27648 + idx];
        int col2 = idx / 864, rem = idx % 864;
        int ci = rem / 27, tap = rem % 27;
        w_s[(tap * 32 + ci) * 32 + col2] = v;
    }
    float acc[8];
    #pragma unroll
    for (int i = 0; i < 8; i++) acc[i] = 0.f;
    int h0 = th * 8, w0 = tw * 8;

    for (int kd = 0; kd < 3; kd++) {
        int dd = d - 1 + kd;
        __syncthreads();
        for (int idx = tid; idx < 3200; idx += 256) {
            int hh = idx / 320; int rem = idx % 320; int ww2 = rem >> 5; int ci = rem & 31;
            int ih = h0 - 1 + hh, iw = w0 - 1 + ww2;
            float v = 0.f;
            if (dd >= 0 && dd < 16 && ih >= 0 && ih < 56 && iw >= 0 && iw < 56)
                v = x[((long)((b * 16 + dd) * 56 + ih) * 56 + iw) * 96 + g * 32 + ci];
            in_s[idx] = v;
        }
        __syncthreads();
        #pragma unroll
        for (int kh = 0; kh < 3; kh++) {
            const float* inrow = &in_s[(hrow + kh) * 320];
            int tb = (kd * 3 + kh) * 3;
            for (int ci = 0; ci < 32; ci++) {
                float wr0 = w_s[((tb + 0) * 32 + ci) * 32 + co_l];
                float wr1 = w_s[((tb + 1) * 32 + ci) * 32 + co_l];
                float wr2 = w_s[((tb + 2) * 32 + ci) * 32 + co_l];
                float rv[10];
                #pragma unroll
                for (int q2 = 0; q2 < 10; q2++) rv[q2] = inrow[q2 * 32 + ci];
                #pragma unroll
                for (int ww2 = 0; ww2 < 8; ww2++)
                    acc[ww2] += rv[ww2] * wr0 + rv[ww2 + 1] * wr1 + rv[ww2 + 2] * wr2;
            }
        }
    }
    long obase = ((long)((b * 16 + d) * 56 + h0 + hrow) * 56 + w0) * 96 + g * 32 + co_l;
    #pragma unroll
    for (int ww2 = 0; ww2 < 8; ww2++) o[obase + ww2 * 96] = acc[ww2];
}

// ---------------- GroupNorm(4) stats: deterministic 2-stage reduction -------
__global__ void gnred_kernel(const float* __restrict__ cv, float* __restrict__ part) {
    __shared__ float ss[256], sqv[256];
    int bg = blockIdx.x / 112, chunk = blockIdx.x % 112;
    int b = bg >> 2, gg = bg & 3;
    long vox0 = (long)b * 50176 + chunk * 448;
    float s = 0.f, q2 = 0.f;
    for (int idx = threadIdx.x; idx < 448 * 24; idx += 256) {
        int v = idx / 24, c2 = idx % 24;
        float val = cv[(vox0 + v) * 96 + gg * 24 + c2];
        s += val; q2 += val * val;
    }
    ss[threadIdx.x] = s; sqv[threadIdx.x] = q2;
    __syncthreads();
    for (int off = 128; off; off >>= 1) {
        if (threadIdx.x < off) {
            ss[threadIdx.x]  += ss[threadIdx.x + off];
            sqv[threadIdx.x] += sqv[threadIdx.x + off];
        }
        __syncthreads();
    }
    if (threadIdx.x == 0) {
        part[blockIdx.x * 2]     = ss[0];
        part[blockIdx.x * 2 + 1] = sqv[0];
    }
}

__global__ void gncomb_kernel(const float* __restrict__ part, float* __restrict__ stats) {
    int t = threadIdx.x;
    if (t < 16) {
        double s = 0.0, q2 = 0.0;
        for (int i = 0; i < 112; i++) {
            s  += (double)part[(t * 112 + i) * 2];
            q2 += (double)part[(t * 112 + i) * 2 + 1];
        }
        double N = 24.0 * 50176.0;
        double mu  = s / N;
        double var = q2 / N - mu * mu;
        stats[t * 2]     = (float)mu;
        stats[t * 2 + 1] = (float)(1.0 / sqrt(var + 1e-5));
    }
}

// ---------------- driver -----------------------------------------------------
extern "C" void kernel_launch(void* const* d_in, const int* in_sizes, int n_in,
                              void* d_out, int out_size) {
    const float* x       = (const float*)d_in[0];
    const float* n1w     = (const float*)d_in[1];
    const float* n1b     = (const float*)d_in[2];
    const float* qkv_w   = (const float*)d_in[3];
    const float* proj_w  = (const float*)d_in[4];
    const float* proj_b  = (const float*)d_in[5];
    const float* conv3_w = (const float*)d_in[6];
    const float* gn_w    = (const float*)d_in[7];
    const float* gn_b    = (const float*)d_in[8];
    const float* convp_w = (const float*)d_in[9];
    const float* n2w     = (const float*)d_in[10];
    const float* n2b     = (const float*)d_in[11];
    const float* fc1_w   = (const float*)d_in[12];
    const float* fc1_b   = (const float*)d_in[13];
    const float* fc2_w   = (const float*)d_in[14];
    const float* fc2_b   = (const float*)d_in[15];
    float* out = (float*)d_out;

    float *p_qkv, *p_attn, *p_x1, *p_conv, *p_x2, *p_part, *p_stats;
    __nv_bfloat16 *p_xnb, *p_attb, *p_cbf, *p_hbf, *p_wq, *p_wp, *p_wc, *p_w1, *p_w2;
    cudaGetSymbolAddress((void**)&p_qkv,  g_qkv);
    cudaGetSymbolAddress((void**)&p_attn, g_attn);
    cudaGetSymbolAddress((void**)&p_x1,   g_x1);
    cudaGetSymbolAddress((void**)&p_conv, g_conv);
    cudaGetSymbolAddress((void**)&p_x2,   g_x2);
    cudaGetSymbolAddress((void**)&p_part, g_part);
    cudaGetSymbolAddress((void**)&p_stats,g_stats);
    cudaGetSymbolAddress((void**)&p_xnb,  g_xnb);
    cudaGetSymbolAddress((void**)&p_attb, g_attb);
    cudaGetSymbolAddress((void**)&p_cbf,  g_cbf);
    cudaGetSymbolAddress((void**)&p_hbf,  g_hbf);
    cudaGetSymbolAddress((void**)&p_wq,   g_wq);
    cudaGetSymbolAddress((void**)&p_wp,   g_wp);
    cudaGetSymbolAddress((void**)&p_wc,   g_wc);
    cudaGetSymbolAddress((void**)&p_w1,   g_w1);
    cudaGetSymbolAddress((void**)&p_w2,   g_w2);

    cudaFuncSetAttribute(conv3_kernel, cudaFuncAttributeMaxDynamicSharedMemorySize, 123392);

    // weight conversions (bf16)
    f2bf_kernel<<<(288*96+255)/256, 256>>>(qkv_w,   p_wq, 288*96);
    f2bf_kernel<<<(96*96+255)/256,  256>>>(proj_w,  p_wp, 96*96);
    f2bf_kernel<<<(96*96+255)/256,  256>>>(convp_w, p_wc, 96*96);
    f2bf_kernel<<<(384*96+255)/256, 256>>>(fc1_w,   p_w1, 384*96);
    f2bf_kernel<<<(96*384+255)/256, 256>>>(fc2_w,   p_w2, 96*384);

    // 1) LN1 -> bf16
    ln_bf_kernel<<<25088, 256>>>(x, n1w, n1b, p_xnb);
    // 2) qkv = xn @ qkv_w^T (fp32 out)
    tgemm<96,0><<<dim3(1568, 3), 256>>>(p_xnb, p_wq, nullptr, nullptr, p_qkv, 288);
    // 3) attention
    attn_kernel<<<dim3(2048, 3), 224>>>(p_qkv, p_attn);
    f2bf_kernel<<<(NTOK*96+255)/256, 256>>>(p_attn, p_attb, NTOK*96);
    // 4) x1 = x + attn @ proj_w^T + proj_b
    tgemm<96,1><<<dim3(1568, 1), 256>>>(p_attb, p_wp, proj_b, x, p_x1, 96);
    // 5) grouped conv
    conv3_kernel<<<9408, 256, 123392>>>(p_x1, conv3_w, p_conv);
    // 6) GN stats
    gnred_kernel<<<1792, 256>>>(p_conv, p_part);
    gncomb_kernel<<<1, 16>>>(p_part, p_stats);
    // 7) GN+ReLU -> bf16, then x2 = x1 + gn @ convp_w^T
    gnrelu_bf_kernel<<<(NTOK*96)/256, 256>>>(p_conv, p_stats, gn_w, gn_b, p_cbf);
    tgemm<96,1><<<dim3(1568, 1), 256>>>(p_cbf, p_wc, nullptr, p_x1, p_x2, 96);
    // 8) LN2 -> bf16
    ln_bf_kernel<<<25088, 256>>>(p_x2, n2w, n2b, p_xnb);
    // 9) h = gelu(xn2 @ fc1_w^T + fc1_b) -> bf16
    tgemm<96,2><<<dim3(1568, 4), 256>>>(p_xnb, p_w1, fc1_b, nullptr, p_hbf, 384);
    // 10) out = x2 + h @ fc2_w^T + fc2_b
    tgemm<384,1><<<dim3(1568, 1), 256>>>(p_hbf, p_w2, fc2_b, p_x2, out, 96);
}

// round 5
// speedup vs baseline: 5.0056x; 3.2224x over previous
#include <cuda_runtime.h>
#include <cuda_bf16.h>
#include <math.h>
#include <cstdint>

// ---------------- problem constants ----------------
#define NTOK 200704           // 4*16*56*56

// ---------------- scratch (static device globals; allowed) ----------------
__device__ float g_x1  [NTOK*96];
__device__ float g_conv[NTOK*96];
__device__ float g_x2  [NTOK*96];
__device__ float g_part[4*4*112*2];
__device__ float g_stats[16*2];
__device__ __nv_bfloat16 g_qkvb[NTOK*288];
__device__ __nv_bfloat16 g_xnb [NTOK*96];
__device__ __nv_bfloat16 g_attb[NTOK*96];
__device__ __nv_bfloat16 g_x1b [NTOK*96];
__device__ __nv_bfloat16 g_cbf [NTOK*96];
__device__ __nv_bfloat16 g_hbf [NTOK*384];
__device__ __nv_bfloat16 g_wq  [288*96];
__device__ __nv_bfloat16 g_wp  [96*96];
__device__ __nv_bfloat16 g_wc  [96*96];
__device__ __nv_bfloat16 g_w1  [384*96];
__device__ __nv_bfloat16 g_w2  [96*384];
__device__ __nv_bfloat16 g_wc3 [96*864];   // conv weights, [co][tap*32+ci]

// ---------------- warp-MMA helpers (arch-agnostic PTX, sm_80+) --------------
__device__ __forceinline__ uint32_t smem_u32(const void* p) {
    uint32_t a;
    asm("{ .reg .u64 t; cvta.to.shared.u64 t, %1; cvt.u32.u64 %0, t; }" : "=r"(a) : "l"(p));
    return a;
}
__device__ __forceinline__ void ldsm_x4(uint32_t* r, uint32_t addr) {
    asm volatile("ldmatrix.sync.aligned.m8n8.x4.shared.b16 {%0,%1,%2,%3}, [%4];"
        : "=r"(r[0]), "=r"(r[1]), "=r"(r[2]), "=r"(r[3]) : "r"(addr));
}
__device__ __forceinline__ void mma16816(float* d, const uint32_t* a, const uint32_t* b) {
    asm volatile(
        "mma.sync.aligned.m16n8k16.row.col.f32.bf16.bf16.f32 "
        "{%0,%1,%2,%3}, {%4,%5,%6,%7}, {%8,%9}, {%0,%1,%2,%3};"
        : "+f"(d[0]), "+f"(d[1]), "+f"(d[2]), "+f"(d[3])
        : "r"(a[0]), "r"(a[1]), "r"(a[2]), "r"(a[3]), "r"(b[0]), "r"(b[1]));
}

// ---------------- tensor-core GEMM: out[M,NO] = epi( A[M,K] @ W[NO,K]^T ) ----
// CTA tile 128x96, 8 warps (4M x 2N), warp tile 32x48. K chunked by 96 in smem.
// EPI: 0 fp32 store; 1 +bias(opt)+resid fp32; 2 gelu(x+bias)->bf16;
//      3 +bias+resid fp32 AND bf16 copy; 4 bf16 store.
template<int KT, int EPI>
__global__ __launch_bounds__(256)
void tgemm(const __nv_bfloat16* __restrict__ A, const __nv_bfloat16* __restrict__ W,
           const float* __restrict__ bias, const float* __restrict__ resid,
           void* __restrict__ outv, __nv_bfloat16* __restrict__ out2, int NOtot) {
    constexpr int KC = 96;
    constexpr int PITCH = KC + 8;     // 104 bf16 = 208 B row pitch (conflict-free)
    __shared__ __nv_bfloat16 As[128 * PITCH];
    __shared__ __nv_bfloat16 Bs[96 * PITCH];
    const int tid = threadIdx.x;
    const int wid = tid >> 5, lane = tid & 31;
    const int warpM = wid & 3, warpN = wid >> 2;
    const long row0 = (long)blockIdx.x * 128;
    const int  col0 = blockIdx.y * 96;

    float acc[2][6][4];
    #pragma unroll
    for (int i = 0; i < 2; i++)
        #pragma unroll
        for (int j = 0; j < 6; j++)
            #pragma unroll
            for (int q = 0; q < 4; q++) acc[i][j][q] = 0.f;

    const uint32_t smA = smem_u32(As), smB = smem_u32(Bs);
    const int t8 = lane & 7, tq = lane >> 3;
    const int rowA_base = warpM * 32 + t8 + (tq & 1) * 8;
    const int koffA = (tq >> 1) * 8;
    uint32_t offA[2];
    #pragma unroll
    for (int mf = 0; mf < 2; mf++)
        offA[mf] = smA + (uint32_t)(((rowA_base + mf * 16) * PITCH + koffA) * 2);
    const int rowB_base = warpN * 48 + t8 + (tq >> 1) * 8;
    const int koffB = (tq & 1) * 8;
    uint32_t offB[3];
    #pragma unroll
    for (int np = 0; np < 3; np++)
        offB[np] = smB + (uint32_t)(((rowB_base + np * 16) * PITCH + koffB) * 2);

    for (int kc = 0; kc < KT; kc += KC) {
        if (kc) __syncthreads();
        #pragma unroll
        for (int it = 0; it < 6; it++) {
            int idx = tid + it * 256;
            int r = idx / 12, k = (idx % 12) * 8;
            uint4 v = *(const uint4*)(A + (row0 + r) * KT + kc + k);
            *(uint4*)(&As[r * PITCH + k]) = v;
        }
        for (int idx = tid; idx < 96 * 12; idx += 256) {
            int n = idx / 12, k = (idx % 12) * 8;
            uint4 v = *(const uint4*)(W + (long)(col0 + n) * KT + kc + k);
            *(uint4*)(&Bs[n * PITCH + k]) = v;
        }
        __syncthreads();
        #pragma unroll
        for (int ks = 0; ks < 6; ks++) {
            uint32_t af[2][4], bf[3][4];
            ldsm_x4(af[0], offA[0] + ks * 32);
            ldsm_x4(af[1], offA[1] + ks * 32);
            ldsm_x4(bf[0], offB[0] + ks * 32);
            ldsm_x4(bf[1], offB[1] + ks * 32);
            ldsm_x4(bf[2], offB[2] + ks * 32);
            #pragma unroll
            for (int mf = 0; mf < 2; mf++)
                #pragma unroll
                for (int np = 0; np < 3; np++) {
                    mma16816(acc[mf][np * 2 + 0], af[mf], &bf[np][0]);
                    mma16816(acc[mf][np * 2 + 1], af[mf], &bf[np][2]);
                }
        }
    }

    const int g = lane >> 2, tig = lane & 3;
    #pragma unroll
    for (int mf = 0; mf < 2; mf++) {
        #pragma unroll
        for (int nf = 0; nf < 6; nf++) {
            int col = col0 + warpN * 48 + nf * 8 + tig * 2;
            #pragma unroll
            for (int h = 0; h < 2; h++) {
                long row = row0 + warpM * 32 + mf * 16 + g + h * 8;
                float v0 = acc[mf][nf][h * 2 + 0];
                float v1 = acc[mf][nf][h * 2 + 1];
                if (EPI == 0) {
                    *(float2*)((float*)outv + row * NOtot + col) = make_float2(v0, v1);
                } else if (EPI == 1 || EPI == 3) {
                    if (bias) { v0 += bias[col]; v1 += bias[col + 1]; }
                    const float2 rr = *(const float2*)(resid + row * NOtot + col);
                    v0 += rr.x; v1 += rr.y;
                    *(float2*)((float*)outv + row * NOtot + col) = make_float2(v0, v1);
                    if (EPI == 3)
                        *(__nv_bfloat162*)(out2 + row * NOtot + col) = __floats2bfloat162_rn(v0, v1);
                } else if (EPI == 2) {
                    v0 += bias[col]; v1 += bias[col + 1];
                    v0 = 0.5f * v0 * (1.f + erff(v0 * 0.70710678118654752f));
                    v1 = 0.5f * v1 * (1.f + erff(v1 * 0.70710678118654752f));
                    *(__nv_bfloat162*)((__nv_bfloat16*)outv + row * NOtot + col) = __floats2bfloat162_rn(v0, v1);
                } else {  // EPI == 4
                    *(__nv_bfloat162*)((__nv_bfloat16*)outv + row * NOtot + col) = __floats2bfloat162_rn(v0, v1);
                }
            }
        }
    }
}

// ---------------- tensor-core grouped 3x3x3 conv (groups=3) -----------------
// Block = (b, 8x8 hw tile, group, d-half). 4 warps; warp w: output rows
// (2w, 2w+1) of the hw tile, all 32 co. Implicit GEMM: A rows = 64 positions
// (per-lane ldmatrix row addresses into the shifted input window), B = weights.
#define CVP 40        // input ci pitch (bf16): 20 words mod 32 -> conflict-free
#define WP3 872       // weight k pitch (bf16): 436 words mod 32 = 20 -> ok
__global__ __launch_bounds__(128)
void conv3t_kernel(const __nv_bfloat16* __restrict__ x, const __nv_bfloat16* __restrict__ wc3,
                   float* __restrict__ o) {
    extern __shared__ char smc[];
    __nv_bfloat16* ws   = (__nv_bfloat16*)smc;             // 32 x WP3
    __nv_bfloat16* in_s = (__nv_bfloat16*)(smc + 32 * WP3 * 2); // 3 planes x 100 x CVP
    int bid = blockIdx.x;
    int g = bid % 3; int t = bid / 3;
    int tw = t % 7, th = (t / 7) % 7, dh = (t / 49) % 2, b = t / 98;
    int h0 = th * 8, w0 = tw * 8, d0 = dh * 8;
    int tid = threadIdx.x, wrp = tid >> 5, lane = tid & 31;

    // weights: 32 co x 864 k (bf16), uint4 loads
    for (int idx = tid; idx < 32 * 108; idx += 128) {
        int row = idx / 108, kc = (idx % 108) * 8;
        uint4 v = *(const uint4*)(wc3 + (g * 32 + row) * 864 + kc);
        *(uint4*)(ws + row * WP3 + kc) = v;
    }

    const int t8 = lane & 7, tq = lane >> 3;
    const int mrow = t8 + (tq & 1) * 8;
    const int p = wrp * 16 + mrow;
    const int hr = p >> 3, wc = p & 7;
    const int koffA = (tq >> 1) * 8;
    const uint32_t inb = smem_u32(in_s);
    const uint32_t aoff = inb + (uint32_t)(((hr * 10 + wc) * CVP + koffA) * 2);
    const int nr = t8 + (tq >> 1) * 8;
    const int koffB = (tq & 1) * 8;
    const uint32_t wsb = smem_u32(ws);
    const uint32_t boff0 = wsb + (uint32_t)((nr * WP3 + koffB) * 2);
    const uint32_t boff1 = wsb + (uint32_t)(((nr + 16) * WP3 + koffB) * 2);
    const int g2 = lane >> 2, tig = lane & 3;

    for (int dl = 0; dl < 8; dl++) {
        int dcur = d0 + dl;
        __syncthreads();   // weights visible (dl=0) / prior mma readers done
        // stage 3 depth planes (halo), 10x10 positions x 32 ci, zero-padded
        for (int idx = tid; idx < 1200; idx += 128) {
            int pl = idx / 400, rem = idx % 400;
            int pos = rem >> 2, c8 = (rem & 3) * 8;
            int hh = pos / 10, ww2 = pos % 10;
            int dde = dcur - 1 + pl, ih = h0 - 1 + hh, iw = w0 - 1 + ww2;
            uint4 v = make_uint4(0, 0, 0, 0);
            if (dde >= 0 && dde < 16 && ih >= 0 && ih < 56 && iw >= 0 && iw < 56)
                v = *(const uint4*)(x + ((long)((b * 16 + dde) * 56 + ih) * 56 + iw) * 96 + g * 32 + c8);
            *(uint4*)(in_s + pl * 4000 + (hh * 10 + ww2) * CVP + c8) = v;
        }
        __syncthreads();

        float acc[4][4];
        #pragma unroll
        for (int i = 0; i < 4; i++)
            #pragma unroll
            for (int q = 0; q < 4; q++) acc[i][q] = 0.f;

        #pragma unroll
        for (int kd = 0; kd < 3; kd++)
            #pragma unroll
            for (int kh = 0; kh < 3; kh++)
                #pragma unroll
                for (int kw = 0; kw < 3; kw++) {
                    uint32_t abase = aoff + (uint32_t)((kd * 4000 + (kh * 10 + kw) * CVP) * 2);
                    int tap = kd * 9 + kh * 3 + kw;
                    #pragma unroll
                    for (int s = 0; s < 2; s++) {
                        uint32_t af[4], b0[4], b1[4];
                        ldsm_x4(af, abase + s * 32);
                        ldsm_x4(b0, boff0 + (uint32_t)((tap * 32 + s * 16) * 2));
                        ldsm_x4(b1, boff1 + (uint32_t)((tap * 32 + s * 16) * 2));
                        mma16816(acc[0], af, &b0[0]);
                        mma16816(acc[1], af, &b0[2]);
                        mma16816(acc[2], af, &b1[0]);
                        mma16816(acc[3], af, &b1[2]);
                    }
                }

        // epilogue: rows (2*wrp + hbit, g2), cols co = nf*8 + tig*2
        #pragma unroll
        for (int hbit = 0; hbit < 2; hbit++) {
            long tok = ((long)(b * 16 + dcur) * 56 + (h0 + 2 * wrp + hbit)) * 56 + (w0 + g2);
            float* orow = o + tok * 96 + g * 32;
            #pragma unroll
            for (int nf = 0; nf < 4; nf++) {
                int co = nf * 8 + tig * 2;
                *(float2*)(orow + co) = make_float2(acc[nf][hbit * 2], acc[nf][hbit * 2 + 1]);
            }
        }
    }
}

// conv weight repack: [co][ci][tap] fp32 -> [co][tap*32+ci] bf16
__global__ void wc3prep_kernel(const float* __restrict__ cw, __nv_bfloat16* __restrict__ o) {
    int idx = blockIdx.x * 256 + threadIdx.x;
    if (idx < 96 * 864) {
        int co = idx / 864, r = idx % 864;
        int tap = r >> 5, ci = r & 31;
        o[idx] = __float2bfloat16(cw[co * 864 + ci * 27 + tap]);
    }
}

// ---------------- LayerNorm over C=96 -> bf16 (1 warp / token) --------------
__global__ void ln_bf_kernel(const float* __restrict__ x, const float* __restrict__ w,
                             const float* __restrict__ b, __nv_bfloat16* __restrict__ o) {
    int wid = threadIdx.x >> 5, lane = threadIdx.x & 31;
    long tok = (long)blockIdx.x * 8 + wid;
    const float* xr = x + tok * 96;
    float v0 = xr[lane], v1 = xr[lane + 32], v2 = xr[lane + 64];
    float s  = v0 + v1 + v2;
    float sq = v0*v0 + v1*v1 + v2*v2;
    #pragma unroll
    for (int off = 16; off; off >>= 1) {
        s  += __shfl_xor_sync(0xFFFFFFFFu, s,  off);
        sq += __shfl_xor_sync(0xFFFFFFFFu, sq, off);
    }
    float mu  = s * (1.f / 96.f);
    float var = sq * (1.f / 96.f) - mu * mu;
    float rs  = rsqrtf(var + 1e-5f);
    __nv_bfloat16* orow = o + tok * 96;
    orow[lane]      = __float2bfloat16((v0 - mu) * rs * w[lane]      + b[lane]);
    orow[lane + 32] = __float2bfloat16((v1 - mu) * rs * w[lane + 32] + b[lane + 32]);
    orow[lane + 64] = __float2bfloat16((v2 - mu) * rs * w[lane + 64] + b[lane + 64]);
}

// ---------------- fp32 -> bf16 ----------------------------------------------
__global__ void f2bf_kernel(const float* __restrict__ a, __nv_bfloat16* __restrict__ o, int n) {
    int i = blockIdx.x * 256 + threadIdx.x;
    if (i < n) o[i] = __float2bfloat16(a[i]);
}

// ---------------- GN(4) + ReLU -> bf16 --------------------------------------
__global__ void gnrelu_bf_kernel(const float* __restrict__ cv, const float* __restrict__ stats,
                                 const float* __restrict__ gnw, const float* __restrict__ gnb,
                                 __nv_bfloat16* __restrict__ o) {
    long i = (long)blockIdx.x * 256 + threadIdx.x;
    long vox = i / 96; int c = (int)(i % 96);
    int gi = (int)(vox / 50176) * 4 + c / 24;
    float v = cv[i];
    v = (v - stats[gi * 2]) * stats[gi * 2 + 1] * gnw[c] + gnb[c];
    o[i] = __float2bfloat16(fmaxf(v, 0.f));
}

// ---------------- multi-dilate local attention (bf16 in/out, fp32 math) -----
__global__ void attn_kernel(const __nv_bfloat16* __restrict__ qkv, __nv_bfloat16* __restrict__ outb) {
    __shared__ int   toks[98];
    __shared__ float ks[98 * 32];
    __shared__ float vs[98 * 32];
    int win = blockIdx.x;
    int dil = blockIdx.y + 1;
    int choff = blockIdx.y * 32;
    int tid = threadIdx.x;
    if (tid < 98) {
        int b  = win >> 9;
        int dq = (win >> 6) & 7;
        int hq = (win >> 3) & 7;
        int wq = win & 7;
        int wd = tid / 49, rem = tid % 49;
        int wh = rem / 7, ww = rem % 7;
        int d = dq * 2 + wd, h = hq * 7 + wh, w = wq * 7 + ww;
        toks[tid] = ((b * 16 + d) * 56 + h) * 56 + w;
    }
    __syncthreads();
    for (int idx = tid; idx < 98 * 32; idx += 224) {
        int n = idx >> 5, c2 = idx & 31;
        long base = (long)toks[n] * 288 + choff + c2;
        ks[idx] = __bfloat162float(qkv[base + 96]);
        vs[idx] = __bfloat162float(qkv[base + 192]);
    }
    __syncthreads();
    if (tid < 196) {
        int n = tid >> 1, head = tid & 1;
        long qbase = (long)toks[n] * 288 + choff + head * 16;
        float q[16];
        #pragma unroll
        for (int c = 0; c < 16; c++) q[c] = __bfloat162float(qkv[qbase + c]);
        float lr[3]; int mm[3];
        #pragma unroll
        for (int j = 0; j < 3; j++) {
            int m = n + (j - 1) * dil;
            mm[j] = m;
            float s = 0.f;
            if (m >= 0 && m < 98) {
                const float* kr = &ks[m * 32 + head * 16];
                #pragma unroll
                for (int c = 0; c < 16; c++) s += q[c] * kr[c];
            }
            lr[j] = s * 0.25f;
        }
        float mx = fmaxf(0.f, fmaxf(lr[0], fmaxf(lr[1], lr[2])));
        float e[3];
        e[0] = expf(lr[0] - mx); e[1] = expf(lr[1] - mx); e[2] = expf(lr[2] - mx);
        float denom = 6.f * expf(-mx) + e[0] + e[1] + e[2];
        float o[16];
        #pragma unroll
        for (int c = 0; c < 16; c++) o[c] = 0.f;
        #pragma unroll
        for (int j = 0; j < 3; j++) {
            int m = mm[j];
            if (m >= 0 && m < 98) {
                float a = e[j] / denom;
                const float* vr = &vs[m * 32 + head * 16];
                #pragma unroll
                for (int c = 0; c < 16; c++) o[c] += a * vr[c];
            }
        }
        long obase = (long)toks[n] * 96 + choff + head * 16;
        #pragma unroll
        for (int c = 0; c < 8; c++)
            *(__nv_bfloat162*)(outb + obase + c * 2) = __floats2bfloat162_rn(o[c * 2], o[c * 2 + 1]);
    }
}

// ---------------- GroupNorm(4) stats: deterministic 2-stage reduction -------
__global__ void gnred_kernel(const float* __restrict__ cv, float* __restrict__ part) {
    __shared__ float ss[256], sqv[256];
    int bg = blockIdx.x / 112, chunk = blockIdx.x % 112;
    int b = bg >> 2, gg = bg & 3;
    long vox0 = (long)b * 50176 + chunk * 448;
    float s = 0.f, q2 = 0.f;
    for (int idx = threadIdx.x; idx < 448 * 24; idx += 256) {
        int v = idx / 24, c2 = idx % 24;
        float val = cv[(vox0 + v) * 96 + gg * 24 + c2];
        s += val; q2 += val * val;
    }
    ss[threadIdx.x] = s; sqv[threadIdx.x] = q2;
    __syncthreads();
    for (int off = 128; off; off >>= 1) {
        if (threadIdx.x < off) {
            ss[threadIdx.x]  += ss[threadIdx.x + off];
            sqv[threadIdx.x] += sqv[threadIdx.x + off];
        }
        __syncthreads();
    }
    if (threadIdx.x == 0) {
        part[blockIdx.x * 2]     = ss[0];
        part[blockIdx.x * 2 + 1] = sqv[0];
    }
}

__global__ void gncomb_kernel(const float* __restrict__ part, float* __restrict__ stats) {
    int t = threadIdx.x;
    if (t < 16) {
        double s = 0.0, q2 = 0.0;
        for (int i = 0; i < 112; i++) {
            s  += (double)part[(t * 112 + i) * 2];
            q2 += (double)part[(t * 112 + i) * 2 + 1];
        }
        double N = 24.0 * 50176.0;
        double mu  = s / N;
        double var = q2 / N - mu * mu;
        stats[t * 2]     = (float)mu;
        stats[t * 2 + 1] = (float)(1.0 / sqrt(var + 1e-5));
    }
}

// ---------------- driver -----------------------------------------------------
extern "C" void kernel_launch(void* const* d_in, const int* in_sizes, int n_in,
                              void* d_out, int out_size) {
    const float* x       = (const float*)d_in[0];
    const float* n1w     = (const float*)d_in[1];
    const float* n1b     = (const float*)d_in[2];
    const float* qkv_w   = (const float*)d_in[3];
    const float* proj_w  = (const float*)d_in[4];
    const float* proj_b  = (const float*)d_in[5];
    const float* conv3_w = (const float*)d_in[6];
    const float* gn_w    = (const float*)d_in[7];
    const float* gn_b    = (const float*)d_in[8];
    const float* convp_w = (const float*)d_in[9];
    const float* n2w     = (const float*)d_in[10];
    const float* n2b     = (const float*)d_in[11];
    const float* fc1_w   = (const float*)d_in[12];
    const float* fc1_b   = (const float*)d_in[13];
    const float* fc2_w   = (const float*)d_in[14];
    const float* fc2_b   = (const float*)d_in[15];
    float* out = (float*)d_out;

    float *p_x1, *p_conv, *p_x2, *p_part, *p_stats;
    __nv_bfloat16 *p_qkvb, *p_xnb, *p_attb, *p_x1b, *p_cbf, *p_hbf;
    __nv_bfloat16 *p_wq, *p_wp, *p_wc, *p_w1, *p_w2, *p_wc3;
    cudaGetSymbolAddress((void**)&p_x1,   g_x1);
    cudaGetSymbolAddress((void**)&p_conv, g_conv);
    cudaGetSymbolAddress((void**)&p_x2,   g_x2);
    cudaGetSymbolAddress((void**)&p_part, g_part);
    cudaGetSymbolAddress((void**)&p_stats,g_stats);
    cudaGetSymbolAddress((void**)&p_qkvb, g_qkvb);
    cudaGetSymbolAddress((void**)&p_xnb,  g_xnb);
    cudaGetSymbolAddress((void**)&p_attb, g_attb);
    cudaGetSymbolAddress((void**)&p_x1b,  g_x1b);
    cudaGetSymbolAddress((void**)&p_cbf,  g_cbf);
    cudaGetSymbolAddress((void**)&p_hbf,  g_hbf);
    cudaGetSymbolAddress((void**)&p_wq,   g_wq);
    cudaGetSymbolAddress((void**)&p_wp,   g_wp);
    cudaGetSymbolAddress((void**)&p_wc,   g_wc);
    cudaGetSymbolAddress((void**)&p_w1,   g_w1);
    cudaGetSymbolAddress((void**)&p_w2,   g_w2);
    cudaGetSymbolAddress((void**)&p_wc3,  g_wc3);

    const int CONV_SMEM = 32 * WP3 * 2 + 3 * 4000 * 2;   // 55808 + 24000 = 79808
    cudaFuncSetAttribute(conv3t_kernel, cudaFuncAttributeMaxDynamicSharedMemorySize, CONV_SMEM);

    // weight conversions (bf16)
    f2bf_kernel<<<(288*96+255)/256, 256>>>(qkv_w,   p_wq, 288*96);
    f2bf_kernel<<<(96*96+255)/256,  256>>>(proj_w,  p_wp, 96*96);
    f2bf_kernel<<<(96*96+255)/256,  256>>>(convp_w, p_wc, 96*96);
    f2bf_kernel<<<(384*96+255)/256, 256>>>(fc1_w,   p_w1, 384*96);
    f2bf_kernel<<<(96*384+255)/256, 256>>>(fc2_w,   p_w2, 96*384);
    wc3prep_kernel<<<(96*864+255)/256, 256>>>(conv3_w, p_wc3);

    // 1) LN1 -> bf16
    ln_bf_kernel<<<25088, 256>>>(x, n1w, n1b, p_xnb);
    // 2) qkv = xn @ qkv_w^T -> bf16
    tgemm<96,4><<<dim3(1568, 3), 256>>>(p_xnb, p_wq, nullptr, nullptr, p_qkvb, nullptr, 288);
    // 3) attention (bf16 in/out)
    attn_kernel<<<dim3(2048, 3), 224>>>(p_qkvb, p_attb);
    // 4) x1 = x + attn @ proj_w^T + proj_b  (fp32 + bf16 copy)
    tgemm<96,3><<<dim3(1568, 1), 256>>>(p_attb, p_wp, proj_b, x, p_x1, p_x1b, 96);
    // 5) grouped conv (tensor cores)
    conv3t_kernel<<<1176, 128, CONV_SMEM>>>(p_x1b, p_wc3, p_conv);
    // 6) GN stats
    gnred_kernel<<<1792, 256>>>(p_conv, p_part);
    gncomb_kernel<<<1, 16>>>(p_part, p_stats);
    // 7) GN+ReLU -> bf16, then x2 = x1 + gn @ convp_w^T
    gnrelu_bf_kernel<<<(NTOK*96)/256, 256>>>(p_conv, p_stats, gn_w, gn_b, p_cbf);
    tgemm<96,1><<<dim3(1568, 1), 256>>>(p_cbf, p_wc, nullptr, p_x1, p_x2, nullptr, 96);
    // 8) LN2 -> bf16
    ln_bf_kernel<<<25088, 256>>>(p_x2, n2w, n2b, p_xnb);
    // 9) h = gelu(xn2 @ fc1_w^T + fc1_b) -> bf16
    tgemm<96,2><<<dim3(1568, 4), 256>>>(p_xnb, p_w1, fc1_b, nullptr, p_hbf, nullptr, 384);
    // 10) out = x2 + h @ fc2_w^T + fc2_b
    tgemm<384,1><<<dim3(1568, 1), 256>>>(p_hbf, p_w2, fc2_b, p_x2, out, nullptr, 96);
}

// round 6
// speedup vs baseline: 5.0941x; 1.0177x over previous
#include <cuda_runtime.h>
#include <cuda_bf16.h>
#include <math.h>
#include <cstdint>

// ---------------- problem constants ----------------
#define NTOK 200704           // 4*16*56*56

// ---------------- scratch (static device globals; allowed) ----------------
__device__ float g_x1  [NTOK*96];
__device__ float g_conv[NTOK*96];
__device__ float g_x2  [NTOK*96];
__device__ float g_part[4*4*112*2];
__device__ float g_stats[16*2];
__device__ __nv_bfloat16 g_qkvb[NTOK*288];
__device__ __nv_bfloat16 g_xnb [NTOK*96];
__device__ __nv_bfloat16 g_attb[NTOK*96];
__device__ __nv_bfloat16 g_x1b [NTOK*96];
__device__ __nv_bfloat16 g_wq  [288*96];
__device__ __nv_bfloat16 g_wp  [96*96];
__device__ __nv_bfloat16 g_wc  [96*96];
__device__ __nv_bfloat16 g_w1  [384*96];
__device__ __nv_bfloat16 g_w2  [96*384];
__device__ __nv_bfloat16 g_wc3 [96*864];   // conv weights, [co][tap*32+ci]

// ---------------- warp-MMA helpers (arch-agnostic PTX, sm_80+) --------------
__device__ __forceinline__ uint32_t smem_u32(const void* p) {
    uint32_t a;
    asm("{ .reg .u64 t; cvta.to.shared.u64 t, %1; cvt.u32.u64 %0, t; }" : "=r"(a) : "l"(p));
    return a;
}
__device__ __forceinline__ void ldsm_x4(uint32_t* r, uint32_t addr) {
    asm volatile("ldmatrix.sync.aligned.m8n8.x4.shared.b16 {%0,%1,%2,%3}, [%4];"
        : "=r"(r[0]), "=r"(r[1]), "=r"(r[2]), "=r"(r[3]) : "r"(addr));
}
__device__ __forceinline__ void mma16816(float* d, const uint32_t* a, const uint32_t* b) {
    asm volatile(
        "mma.sync.aligned.m16n8k16.row.col.f32.bf16.bf16.f32 "
        "{%0,%1,%2,%3}, {%4,%5,%6,%7}, {%8,%9}, {%0,%1,%2,%3};"
        : "+f"(d[0]), "+f"(d[1]), "+f"(d[2]), "+f"(d[3])
        : "r"(a[0]), "r"(a[1]), "r"(a[2]), "r"(a[3]), "r"(b[0]), "r"(b[1]));
}
__device__ __forceinline__ float gelu_exact(float v) {
    return 0.5f * v * (1.f + erff(v * 0.70710678118654752f));
}

// ---------------- tensor-core GEMM: out[M,NO] = epi( A[M,K] @ W[NO,K]^T ) ----
// CTA tile 128x96, 8 warps (4M x 2N), warp tile 32x48. K chunked by 96 in smem.
// EPI: 3 = +bias+resid fp32 AND bf16 copy; 4 = bf16 store.
template<int KT, int EPI>
__global__ __launch_bounds__(256)
void tgemm(const __nv_bfloat16* __restrict__ A, const __nv_bfloat16* __restrict__ W,
           const float* __restrict__ bias, const float* __restrict__ resid,
           void* __restrict__ outv, __nv_bfloat16* __restrict__ out2, int NOtot) {
    constexpr int KC = 96;
    constexpr int PITCH = KC + 8;
    __shared__ __nv_bfloat16 As[128 * PITCH];
    __shared__ __nv_bfloat16 Bs[96 * PITCH];
    const int tid = threadIdx.x;
    const int wid = tid >> 5, lane = tid & 31;
    const int warpM = wid & 3, warpN = wid >> 2;
    const long row0 = (long)blockIdx.x * 128;
    const int  col0 = blockIdx.y * 96;

    float acc[2][6][4];
    #pragma unroll
    for (int i = 0; i < 2; i++)
        #pragma unroll
        for (int j = 0; j < 6; j++)
            #pragma unroll
            for (int q = 0; q < 4; q++) acc[i][j][q] = 0.f;

    const uint32_t smA = smem_u32(As), smB = smem_u32(Bs);
    const int t8 = lane & 7, tq = lane >> 3;
    const int rowA_base = warpM * 32 + t8 + (tq & 1) * 8;
    const int koffA = (tq >> 1) * 8;
    uint32_t offA[2];
    #pragma unroll
    for (int mf = 0; mf < 2; mf++)
        offA[mf] = smA + (uint32_t)(((rowA_base + mf * 16) * PITCH + koffA) * 2);
    const int rowB_base = warpN * 48 + t8 + (tq >> 1) * 8;
    const int koffB = (tq & 1) * 8;
    uint32_t offB[3];
    #pragma unroll
    for (int np = 0; np < 3; np++)
        offB[np] = smB + (uint32_t)(((rowB_base + np * 16) * PITCH + koffB) * 2);

    for (int kc = 0; kc < KT; kc += KC) {
        if (kc) __syncthreads();
        #pragma unroll
        for (int it = 0; it < 6; it++) {
            int idx = tid + it * 256;
            int r = idx / 12, k = (idx % 12) * 8;
            uint4 v = *(const uint4*)(A + (row0 + r) * KT + kc + k);
            *(uint4*)(&As[r * PITCH + k]) = v;
        }
        for (int idx = tid; idx < 96 * 12; idx += 256) {
            int n = idx / 12, k = (idx % 12) * 8;
            uint4 v = *(const uint4*)(W + (long)(col0 + n) * KT + kc + k);
            *(uint4*)(&Bs[n * PITCH + k]) = v;
        }
        __syncthreads();
        #pragma unroll
        for (int ks = 0; ks < 6; ks++) {
            uint32_t af[2][4], bf[3][4];
            ldsm_x4(af[0], offA[0] + ks * 32);
            ldsm_x4(af[1], offA[1] + ks * 32);
            ldsm_x4(bf[0], offB[0] + ks * 32);
            ldsm_x4(bf[1], offB[1] + ks * 32);
            ldsm_x4(bf[2], offB[2] + ks * 32);
            #pragma unroll
            for (int mf = 0; mf < 2; mf++)
                #pragma unroll
                for (int np = 0; np < 3; np++) {
                    mma16816(acc[mf][np * 2 + 0], af[mf], &bf[np][0]);
                    mma16816(acc[mf][np * 2 + 1], af[mf], &bf[np][2]);
                }
        }
    }

    const int g = lane >> 2, tig = lane & 3;
    #pragma unroll
    for (int mf = 0; mf < 2; mf++) {
        #pragma unroll
        for (int nf = 0; nf < 6; nf++) {
            int col = col0 + warpN * 48 + nf * 8 + tig * 2;
            #pragma unroll
            for (int h = 0; h < 2; h++) {
                long row = row0 + warpM * 32 + mf * 16 + g + h * 8;
                float v0 = acc[mf][nf][h * 2 + 0];
                float v1 = acc[mf][nf][h * 2 + 1];
                if (EPI == 3) {
                    if (bias) { v0 += bias[col]; v1 += bias[col + 1]; }
                    const float2 rr = *(const float2*)(resid + row * NOtot + col);
                    v0 += rr.x; v1 += rr.y;
                    *(float2*)((float*)outv + row * NOtot + col) = make_float2(v0, v1);
                    *(__nv_bfloat162*)(out2 + row * NOtot + col) = __floats2bfloat162_rn(v0, v1);
                } else {  // EPI == 4
                    *(__nv_bfloat162*)((__nv_bfloat16*)outv + row * NOtot + col) = __floats2bfloat162_rn(v0, v1);
                }
            }
        }
    }
}

// ---------------- fused 1x1-conv GEMM: GN+ReLU prologue, LN2 epilogue -------
// x2 = x1 + relu(GN(conv)) @ wc^T ; xnb = LayerNorm(x2, n2w, n2b) -> bf16
__global__ __launch_bounds__(256)
void convp_kernel(const float* __restrict__ conv, const __nv_bfloat16* __restrict__ W,
                  const float* __restrict__ stats, const float* __restrict__ gnw,
                  const float* __restrict__ gnb, const float* __restrict__ x1,
                  const float* __restrict__ n2w, const float* __restrict__ n2b,
                  float* __restrict__ x2, __nv_bfloat16* __restrict__ xnb) {
    constexpr int PITCH = 104;
    __shared__ __nv_bfloat16 As[128 * PITCH];
    __shared__ __nv_bfloat16 Bs[96 * PITCH];
    __shared__ float redS[128][2], redQ[128][2];
    const int tid = threadIdx.x;
    const int wid = tid >> 5, lane = tid & 31;
    const int warpM = wid & 3, warpN = wid >> 2;
    const long row0 = (long)blockIdx.x * 128;

    // stage A with GN + ReLU -> bf16
    const int bidx = (int)(row0 / 50176) * 4;           // all 128 rows same batch (128 | 50176)
    for (int idx = tid; idx < 128 * 24; idx += 256) {
        int r = idx / 24, k4 = (idx % 24) * 4;
        const float4 cv = *(const float4*)(conv + (row0 + r) * 96 + k4);
        int gi = bidx + k4 / 24;
        float mu = stats[gi * 2], rs = stats[gi * 2 + 1];
        float f0 = fmaxf((cv.x - mu) * rs * gnw[k4]     + gnb[k4],     0.f);
        float f1 = fmaxf((cv.y - mu) * rs * gnw[k4 + 1] + gnb[k4 + 1], 0.f);
        float f2 = fmaxf((cv.z - mu) * rs * gnw[k4 + 2] + gnb[k4 + 2], 0.f);
        float f3 = fmaxf((cv.w - mu) * rs * gnw[k4 + 3] + gnb[k4 + 3], 0.f);
        *(__nv_bfloat162*)(&As[r * PITCH + k4])     = __floats2bfloat162_rn(f0, f1);
        *(__nv_bfloat162*)(&As[r * PITCH + k4 + 2]) = __floats2bfloat162_rn(f2, f3);
    }
    for (int idx = tid; idx < 96 * 12; idx += 256) {
        int n = idx / 12, k = (idx % 12) * 8;
        uint4 v = *(const uint4*)(W + n * 96 + k);
        *(uint4*)(&Bs[n * PITCH + k]) = v;
    }
    __syncthreads();

    float acc[2][6][4];
    #pragma unroll
    for (int i = 0; i < 2; i++)
        #pragma unroll
        for (int j = 0; j < 6; j++)
            #pragma unroll
            for (int q = 0; q < 4; q++) acc[i][j][q] = 0.f;

    const uint32_t smA = smem_u32(As), smB = smem_u32(Bs);
    const int t8 = lane & 7, tq = lane >> 3;
    const int rowA_base = warpM * 32 + t8 + (tq & 1) * 8;
    const int koffA = (tq >> 1) * 8;
    uint32_t offA[2];
    #pragma unroll
    for (int mf = 0; mf < 2; mf++)
        offA[mf] = smA + (uint32_t)(((rowA_base + mf * 16) * PITCH + koffA) * 2);
    const int rowB_base = warpN * 48 + t8 + (tq >> 1) * 8;
    const int koffB = (tq & 1) * 8;
    uint32_t offB[3];
    #pragma unroll
    for (int np = 0; np < 3; np++)
        offB[np] = smB + (uint32_t)(((rowB_base + np * 16) * PITCH + koffB) * 2);

    #pragma unroll
    for (int ks = 0; ks < 6; ks++) {
        uint32_t af[2][4], bf[3][4];
        ldsm_x4(af[0], offA[0] + ks * 32);
        ldsm_x4(af[1], offA[1] + ks * 32);
        ldsm_x4(bf[0], offB[0] + ks * 32);
        ldsm_x4(bf[1], offB[1] + ks * 32);
        ldsm_x4(bf[2], offB[2] + ks * 32);
        #pragma unroll
        for (int mf = 0; mf < 2; mf++)
            #pragma unroll
            for (int np = 0; np < 3; np++) {
                mma16816(acc[mf][np * 2 + 0], af[mf], &bf[np][0]);
                mma16816(acc[mf][np * 2 + 1], af[mf], &bf[np][2]);
            }
    }

    // add residual -> x2 values held in acc; per-row partial sums
    const int g = lane >> 2, tig = lane & 3;
    #pragma unroll
    for (int mf = 0; mf < 2; mf++)
        #pragma unroll
        for (int h = 0; h < 2; h++) {
            int rl = warpM * 32 + mf * 16 + g + h * 8;
            long row = row0 + rl;
            float s = 0.f, q2 = 0.f;
            #pragma unroll
            for (int nf = 0; nf < 6; nf++) {
                int col = warpN * 48 + nf * 8 + tig * 2;
                const float2 rr = *(const float2*)(x1 + row * 96 + col);
                float v0 = acc[mf][nf][h * 2 + 0] + rr.x;
                float v1 = acc[mf][nf][h * 2 + 1] + rr.y;
                acc[mf][nf][h * 2 + 0] = v0;
                acc[mf][nf][h * 2 + 1] = v1;
                s += v0 + v1; q2 += v0 * v0 + v1 * v1;
            }
            s  += __shfl_xor_sync(0xFFFFFFFFu, s, 1);
            q2 += __shfl_xor_sync(0xFFFFFFFFu, q2, 1);
            s  += __shfl_xor_sync(0xFFFFFFFFu, s, 2);
            q2 += __shfl_xor_sync(0xFFFFFFFFu, q2, 2);
            if (tig == 0) { redS[rl][warpN] = s; redQ[rl][warpN] = q2; }
        }
    __syncthreads();

    #pragma unroll
    for (int mf = 0; mf < 2; mf++)
        #pragma unroll
        for (int h = 0; h < 2; h++) {
            int rl = warpM * 32 + mf * 16 + g + h * 8;
            long row = row0 + rl;
            float tot = redS[rl][0] + redS[rl][1];
            float tq2 = redQ[rl][0] + redQ[rl][1];
            float mu = tot * (1.f / 96.f);
            float var = tq2 * (1.f / 96.f) - mu * mu;
            float rs = rsqrtf(var + 1e-5f);
            #pragma unroll
            for (int nf = 0; nf < 6; nf++) {
                int col = warpN * 48 + nf * 8 + tig * 2;
                float v0 = acc[mf][nf][h * 2 + 0];
                float v1 = acc[mf][nf][h * 2 + 1];
                *(float2*)(x2 + row * 96 + col) = make_float2(v0, v1);
                float n0 = (v0 - mu) * rs * n2w[col]     + n2b[col];
                float n1 = (v1 - mu) * rs * n2w[col + 1] + n2b[col + 1];
                *(__nv_bfloat162*)(xnb + row * 96 + col) = __floats2bfloat162_rn(n0, n1);
            }
        }
}

// ---------------- fused MLP: out = x2 + gelu(xn@W1^T+b1) @ W2^T + b2 --------
__global__ __launch_bounds__(256)
void fc12_kernel(const __nv_bfloat16* __restrict__ xnb, const __nv_bfloat16* __restrict__ w1,
                 const __nv_bfloat16* __restrict__ w2, const float* __restrict__ b1,
                 const float* __restrict__ b2, const float* __restrict__ x2,
                 float* __restrict__ out) {
    constexpr int PITCH = 104, HPITCH = 392;
    extern __shared__ char sm[];
    __nv_bfloat16* As = (__nv_bfloat16*)sm;                       // 128*104
    __nv_bfloat16* Bs = (__nv_bfloat16*)(sm + 26624);             // 96*104
    __nv_bfloat16* Hs = (__nv_bfloat16*)(sm + 26624 + 19968);     // 128*392
    const int tid = threadIdx.x;
    const int wid = tid >> 5, lane = tid & 31;
    const int warpM = wid & 3, warpN = wid >> 2;
    const long row0 = (long)blockIdx.x * 128;

    // load xn tile once
    #pragma unroll
    for (int it = 0; it < 6; it++) {
        int idx = tid + it * 256;
        int r = idx / 12, k = (idx % 12) * 8;
        uint4 v = *(const uint4*)(xnb + (row0 + r) * 96 + k);
        *(uint4*)(&As[r * PITCH + k]) = v;
    }

    const uint32_t smA = smem_u32(As), smB = smem_u32(Bs), smH = smem_u32(Hs);
    const int t8 = lane & 7, tq = lane >> 3;
    const int rowA_base = warpM * 32 + t8 + (tq & 1) * 8;
    const int koffA = (tq >> 1) * 8;
    uint32_t offA[2], offH[2];
    #pragma unroll
    for (int mf = 0; mf < 2; mf++) {
        offA[mf] = smA + (uint32_t)(((rowA_base + mf * 16) * PITCH  + koffA) * 2);
        offH[mf] = smH + (uint32_t)(((rowA_base + mf * 16) * HPITCH + koffA) * 2);
    }
    const int rowB_base = warpN * 48 + t8 + (tq >> 1) * 8;
    const int koffB = (tq & 1) * 8;
    uint32_t offB[3];
    #pragma unroll
    for (int np = 0; np < 3; np++)
        offB[np] = smB + (uint32_t)(((rowB_base + np * 16) * PITCH + koffB) * 2);

    const int g = lane >> 2, tig = lane & 3;

    // ---- stage 1: h = gelu(xn @ W1^T + b1), 4 chunks of 96 hidden ----
    for (int nc = 0; nc < 4; nc++) {
        __syncthreads();   // As visible (nc=0) / previous Bs consumers done
        for (int idx = tid; idx < 96 * 12; idx += 256) {
            int n = idx / 12, k = (idx % 12) * 8;
            uint4 v = *(const uint4*)(w1 + (nc * 96 + n) * 96 + k);
            *(uint4*)(&Bs[n * PITCH + k]) = v;
        }
        __syncthreads();
        float acc[2][6][4];
        #pragma unroll
        for (int i = 0; i < 2; i++)
            #pragma unroll
            for (int j = 0; j < 6; j++)
                #pragma unroll
                for (int q = 0; q < 4; q++) acc[i][j][q] = 0.f;
        #pragma unroll
        for (int ks = 0; ks < 6; ks++) {
            uint32_t af[2][4], bf[3][4];
            ldsm_x4(af[0], offA[0] + ks * 32);
            ldsm_x4(af[1], offA[1] + ks * 32);
            ldsm_x4(bf[0], offB[0] + ks * 32);
            ldsm_x4(bf[1], offB[1] + ks * 32);
            ldsm_x4(bf[2], offB[2] + ks * 32);
            #pragma unroll
            for (int mf = 0; mf < 2; mf++)
                #pragma unroll
                for (int np = 0; np < 3; np++) {
                    mma16816(acc[mf][np * 2 + 0], af[mf], &bf[np][0]);
                    mma16816(acc[mf][np * 2 + 1], af[mf], &bf[np][2]);
                }
        }
        #pragma unroll
        for (int mf = 0; mf < 2; mf++)
            #pragma unroll
            for (int nf = 0; nf < 6; nf++) {
                int hcol = nc * 96 + warpN * 48 + nf * 8 + tig * 2;
                float bb0 = b1[hcol], bb1 = b1[hcol + 1];
                #pragma unroll
                for (int h = 0; h < 2; h++) {
                    int rl = warpM * 32 + mf * 16 + g + h * 8;
                    float v0 = gelu_exact(acc[mf][nf][h * 2 + 0] + bb0);
                    float v1 = gelu_exact(acc[mf][nf][h * 2 + 1] + bb1);
                    *(__nv_bfloat162*)(&Hs[rl * HPITCH + hcol]) = __floats2bfloat162_rn(v0, v1);
                }
            }
    }

    // ---- stage 2: out = h @ W2^T + b2 + x2 ----
    float acc[2][6][4];
    #pragma unroll
    for (int i = 0; i < 2; i++)
        #pragma unroll
        for (int j = 0; j < 6; j++)
            #pragma unroll
            for (int q = 0; q < 4; q++) acc[i][j][q] = 0.f;

    for (int kc = 0; kc < 4; kc++) {
        __syncthreads();   // H writes visible / previous Bs consumers done
        for (int idx = tid; idx < 96 * 12; idx += 256) {
            int n = idx / 12, k = (idx % 12) * 8;
            uint4 v = *(const uint4*)(w2 + n * 384 + kc * 96 + k);
            *(uint4*)(&Bs[n * PITCH + k]) = v;
        }
        __syncthreads();
        #pragma unroll
        for (int ks = 0; ks < 6; ks++) {
            uint32_t af[2][4], bf[3][4];
            ldsm_x4(af[0], offH[0] + kc * 192 + ks * 32);
            ldsm_x4(af[1], offH[1] + kc * 192 + ks * 32);
            ldsm_x4(bf[0], offB[0] + ks * 32);
            ldsm_x4(bf[1], offB[1] + ks * 32);
            ldsm_x4(bf[2], offB[2] + ks * 32);
            #pragma unroll
            for (int mf = 0; mf < 2; mf++)
                #pragma unroll
                for (int np = 0; np < 3; np++) {
                    mma16816(acc[mf][np * 2 + 0], af[mf], &bf[np][0]);
                    mma16816(acc[mf][np * 2 + 1], af[mf], &bf[np][2]);
                }
        }
    }

    #pragma unroll
    for (int mf = 0; mf < 2; mf++)
        #pragma unroll
        for (int nf = 0; nf < 6; nf++) {
            int col = warpN * 48 + nf * 8 + tig * 2;
            #pragma unroll
            for (int h = 0; h < 2; h++) {
                long row = row0 + warpM * 32 + mf * 16 + g + h * 8;
                const float2 rr = *(const float2*)(x2 + row * 96 + col);
                float v0 = acc[mf][nf][h * 2 + 0] + b2[col]     + rr.x;
                float v1 = acc[mf][nf][h * 2 + 1] + b2[col + 1] + rr.y;
                *(float2*)(out + row * 96 + col) = make_float2(v0, v1);
            }
        }
}

// ---------------- tensor-core grouped 3x3x3 conv, rolling depth planes ------
#define CVP 40        // input ci pitch (bf16)
#define WP3 872       // weight k pitch (bf16)
__global__ __launch_bounds__(128)
void conv3t_kernel(const __nv_bfloat16* __restrict__ x, const __nv_bfloat16* __restrict__ wc3,
                   float* __restrict__ o) {
    extern __shared__ char smc[];
    __nv_bfloat16* ws   = (__nv_bfloat16*)smc;                   // 32 x WP3
    __nv_bfloat16* in_s = (__nv_bfloat16*)(smc + 32 * WP3 * 2);  // 3 slots x 100 x CVP
    int bid = blockIdx.x;
    int g = bid % 3; int t = bid / 3;
    int tw = t % 7, th = (t / 7) % 7, dh = (t / 49) % 2, b = t / 98;
    int h0 = th * 8, w0 = tw * 8, d0 = dh * 8;
    int tid = threadIdx.x, wrp = tid >> 5, lane = tid & 31;

    for (int idx = tid; idx < 32 * 108; idx += 128) {
        int row = idx / 108, kc = (idx % 108) * 8;
        uint4 v = *(const uint4*)(wc3 + (g * 32 + row) * 864 + kc);
        *(uint4*)(ws + row * WP3 + kc) = v;
    }

    // plane loader: 100 positions x 32 ci (uint4 = 8 ci), zero-padded
    auto load_plane = [&](int dde, int slot) {
        for (int idx = tid; idx < 400; idx += 128) {
            int pos = idx >> 2, c8 = (idx & 3) * 8;
            int hh = pos / 10, ww2 = pos % 10;
            int ih = h0 - 1 + hh, iw = w0 - 1 + ww2;
            uint4 v = make_uint4(0, 0, 0, 0);
            if (dde >= 0 && dde < 16 && ih >= 0 && ih < 56 && iw >= 0 && iw < 56)
                v = *(const uint4*)(x + ((long)((b * 16 + dde) * 56 + ih) * 56 + iw) * 96 + g * 32 + c8);
            *(uint4*)(in_s + slot * 4000 + (hh * 10 + ww2) * CVP + c8) = v;
        }
    };
    load_plane(d0 - 1, (d0 + 2) % 3);
    load_plane(d0,      d0 % 3);

    const int t8 = lane & 7, tq = lane >> 3;
    const int mrow = t8 + (tq & 1) * 8;
    const int p = wrp * 16 + mrow;
    const int hr = p >> 3, wc = p & 7;
    const int koffA = (tq >> 1) * 8;
    const uint32_t inb = smem_u32(in_s);
    const uint32_t aoff = inb + (uint32_t)(((hr * 10 + wc) * CVP + koffA) * 2);
    const int nr = t8 + (tq >> 1) * 8;
    const int koffB = (tq & 1) * 8;
    const uint32_t wsb = smem_u32(ws);
    const uint32_t boff0 = wsb + (uint32_t)((nr * WP3 + koffB) * 2);
    const uint32_t boff1 = wsb + (uint32_t)(((nr + 16) * WP3 + koffB) * 2);
    const int g2 = lane >> 2, tig = lane & 3;

    for (int dl = 0; dl < 8; dl++) {
        int dcur = d0 + dl;
        __syncthreads();                      // prior compute done (slot free)
        load_plane(dcur + 1, (dcur + 1) % 3);
        __syncthreads();                      // all stores visible

        int sl0 = (dcur + 2) % 3, sl1 = dcur % 3, sl2 = (dcur + 1) % 3;
        int slots[3] = { sl0, sl1, sl2 };

        float acc[4][4];
        #pragma unroll
        for (int i = 0; i < 4; i++)
            #pragma unroll
            for (int q = 0; q < 4; q++) acc[i][q] = 0.f;

        #pragma unroll
        for (int kd = 0; kd < 3; kd++)
            #pragma unroll
            for (int kh = 0; kh < 3; kh++)
                #pragma unroll
                for (int kw = 0; kw < 3; kw++) {
                    uint32_t abase = aoff + (uint32_t)((slots[kd] * 4000 + (kh * 10 + kw) * CVP) * 2);
                    int tap = kd * 9 + kh * 3 + kw;
                    #pragma unroll
                    for (int s = 0; s < 2; s++) {
                        uint32_t af[4], b0[4], b1[4];
                        ldsm_x4(af, abase + s * 32);
                        ldsm_x4(b0, boff0 + (uint32_t)((tap * 32 + s * 16) * 2));
                        ldsm_x4(b1, boff1 + (uint32_t)((tap * 32 + s * 16) * 2));
                        mma16816(acc[0], af, &b0[0]);
                        mma16816(acc[1], af, &b0[2]);
                        mma16816(acc[2], af, &b1[0]);
                        mma16816(acc[3], af, &b1[2]);
                    }
                }

        #pragma unroll
        for (int hbit = 0; hbit < 2; hbit++) {
            long tok = ((long)(b * 16 + dcur) * 56 + (h0 + 2 * wrp + hbit)) * 56 + (w0 + g2);
            float* orow = o + tok * 96 + g * 32;
            #pragma unroll
            for (int nf = 0; nf < 4; nf++) {
                int co = nf * 8 + tig * 2;
                *(float2*)(orow + co) = make_float2(acc[nf][hbit * 2], acc[nf][hbit * 2 + 1]);
            }
        }
    }
}

// conv weight repack: [co][ci][tap] fp32 -> [co][tap*32+ci] bf16
__global__ void wc3prep_kernel(const float* __restrict__ cw, __nv_bfloat16* __restrict__ o) {
    int idx = blockIdx.x * 256 + threadIdx.x;
    if (idx < 96 * 864) {
        int co = idx / 864, r = idx % 864;
        int tap = r >> 5, ci = r & 31;
        o[idx] = __float2bfloat16(cw[co * 864 + ci * 27 + tap]);
    }
}

// ---------------- LayerNorm over C=96 -> bf16 (1 warp / token) --------------
__global__ void ln_bf_kernel(const float* __restrict__ x, const float* __restrict__ w,
                             const float* __restrict__ b, __nv_bfloat16* __restrict__ o) {
    int wid = threadIdx.x >> 5, lane = threadIdx.x & 31;
    long tok = (long)blockIdx.x * 8 + wid;
    const float* xr = x + tok * 96;
    float v0 = xr[lane], v1 = xr[lane + 32], v2 = xr[lane + 64];
    float s  = v0 + v1 + v2;
    float sq = v0*v0 + v1*v1 + v2*v2;
    #pragma unroll
    for (int off = 16; off; off >>= 1) {
        s  += __shfl_xor_sync(0xFFFFFFFFu, s,  off);
        sq += __shfl_xor_sync(0xFFFFFFFFu, sq, off);
    }
    float mu  = s * (1.f / 96.f);
    float var = sq * (1.f / 96.f) - mu * mu;
    float rs  = rsqrtf(var + 1e-5f);
    __nv_bfloat16* orow = o + tok * 96;
    orow[lane]      = __float2bfloat16((v0 - mu) * rs * w[lane]      + b[lane]);
    orow[lane + 32] = __float2bfloat16((v1 - mu) * rs * w[lane + 32] + b[lane + 32]);
    orow[lane + 64] = __float2bfloat16((v2 - mu) * rs * w[lane + 64] + b[lane + 64]);
}

// ---------------- fp32 -> bf16 ----------------------------------------------
__global__ void f2bf_kernel(const float* __restrict__ a, __nv_bfloat16* __restrict__ o, int n) {
    int i = blockIdx.x * 256 + threadIdx.x;
    if (i < n) o[i] = __float2bfloat16(a[i]);
}

// ---------------- multi-dilate local attention (bf16 in/out, fp32 math) -----
__global__ void attn_kernel(const __nv_bfloat16* __restrict__ qkv, __nv_bfloat16* __restrict__ outb) {
    __shared__ int   toks[98];
    __shared__ float ks[98 * 32];
    __shared__ float vs[98 * 32];
    int win = blockIdx.x;
    int dil = blockIdx.y + 1;
    int choff = blockIdx.y * 32;
    int tid = threadIdx.x;
    if (tid < 98) {
        int b  = win >> 9;
        int dq = (win >> 6) & 7;
        int hq = (win >> 3) & 7;
        int wq = win & 7;
        int wd = tid / 49, rem = tid % 49;
        int wh = rem / 7, ww = rem % 7;
        int d = dq * 2 + wd, h = hq * 7 + wh, w = wq * 7 + ww;
        toks[tid] = ((b * 16 + d) * 56 + h) * 56 + w;
    }
    __syncthreads();
    for (int idx = tid; idx < 98 * 32; idx += 224) {
        int n = idx >> 5, c2 = idx & 31;
        long base = (long)toks[n] * 288 + choff + c2;
        ks[idx] = __bfloat162float(qkv[base + 96]);
        vs[idx] = __bfloat162float(qkv[base + 192]);
    }
    __syncthreads();
    if (tid < 196) {
        int n = tid >> 1, head = tid & 1;
        long qbase = (long)toks[n] * 288 + choff + head * 16;
        float q[16];
        #pragma unroll
        for (int c = 0; c < 16; c++) q[c] = __bfloat162float(qkv[qbase + c]);
        float lr[3]; int mm[3];
        #pragma unroll
        for (int j = 0; j < 3; j++) {
            int m = n + (j - 1) * dil;
            mm[j] = m;
            float s = 0.f;
            if (m >= 0 && m < 98) {
                const float* kr = &ks[m * 32 + head * 16];
                #pragma unroll
                for (int c = 0; c < 16; c++) s += q[c] * kr[c];
            }
            lr[j] = s * 0.25f;
        }
        float mx = fmaxf(0.f, fmaxf(lr[0], fmaxf(lr[1], lr[2])));
        float e[3];
        e[0] = expf(lr[0] - mx); e[1] = expf(lr[1] - mx); e[2] = expf(lr[2] - mx);
        float denom = 6.f * expf(-mx) + e[0] + e[1] + e[2];
        float o[16];
        #pragma unroll
        for (int c = 0; c < 16; c++) o[c] = 0.f;
        #pragma unroll
        for (int j = 0; j < 3; j++) {
            int m = mm[j];
            if (m >= 0 && m < 98) {
                float a = e[j] / denom;
                const float* vr = &vs[m * 32 + head * 16];
                #pragma unroll
                for (int c = 0; c < 16; c++) o[c] += a * vr[c];
            }
        }
        long obase = (long)toks[n] * 96 + choff + head * 16;
        #pragma unroll
        for (int c = 0; c < 8; c++)
            *(__nv_bfloat162*)(outb + obase + c * 2) = __floats2bfloat162_rn(o[c * 2], o[c * 2 + 1]);
    }
}

// ---------------- GroupNorm(4) stats: deterministic 2-stage reduction -------
__global__ void gnred_kernel(const float* __restrict__ cv, float* __restrict__ part) {
    __shared__ float ss[256], sqv[256];
    int bg = blockIdx.x / 112, chunk = blockIdx.x % 112;
    int b = bg >> 2, gg = bg & 3;
    long vox0 = (long)b * 50176 + chunk * 448;
    float s = 0.f, q2 = 0.f;
    for (int idx = threadIdx.x; idx < 448 * 24; idx += 256) {
        int v = idx / 24, c2 = idx % 24;
        float val = cv[(vox0 + v) * 96 + gg * 24 + c2];
        s += val; q2 += val * val;
    }
    ss[threadIdx.x] = s; sqv[threadIdx.x] = q2;
    __syncthreads();
    for (int off = 128; off; off >>= 1) {
        if (threadIdx.x < off) {
            ss[threadIdx.x]  += ss[threadIdx.x + off];
            sqv[threadIdx.x] += sqv[threadIdx.x + off];
        }
        __syncthreads();
    }
    if (threadIdx.x == 0) {
        part[blockIdx.x * 2]     = ss[0];
        part[blockIdx.x * 2 + 1] = sqv[0];
    }
}

__global__ void gncomb_kernel(const float* __restrict__ part, float* __restrict__ stats) {
    int t = threadIdx.x;
    if (t < 16) {
        double s = 0.0, q2 = 0.0;
        for (int i = 0; i < 112; i++) {
            s  += (double)part[(t * 112 + i) * 2];
            q2 += (double)part[(t * 112 + i) * 2 + 1];
        }
        double N = 24.0 * 50176.0;
        double mu  = s / N;
        double var = q2 / N - mu * mu;
        stats[t * 2]     = (float)mu;
        stats[t * 2 + 1] = (float)(1.0 / sqrt(var + 1e-5));
    }
}

// ---------------- driver -----------------------------------------------------
extern "C" void kernel_launch(void* const* d_in, const int* in_sizes, int n_in,
                              void* d_out, int out_size) {
    const float* x       = (const float*)d_in[0];
    const float* n1w     = (const float*)d_in[1];
    const float* n1b     = (const float*)d_in[2];
    const float* qkv_w   = (const float*)d_in[3];
    const float* proj_w  = (const float*)d_in[4];
    const float* proj_b  = (const float*)d_in[5];
    const float* conv3_w = (const float*)d_in[6];
    const float* gn_w    = (const float*)d_in[7];
    const float* gn_b    = (const float*)d_in[8];
    const float* convp_w = (const float*)d_in[9];
    const float* n2w     = (const float*)d_in[10];
    const float* n2b     = (const float*)d_in[11];
    const float* fc1_w   = (const float*)d_in[12];
    const float* fc1_b   = (const float*)d_in[13];
    const float* fc2_w   = (const float*)d_in[14];
    const float* fc2_b   = (const float*)d_in[15];
    float* out = (float*)d_out;

    float *p_x1, *p_conv, *p_x2, *p_part, *p_stats;
    __nv_bfloat16 *p_qkvb, *p_xnb, *p_attb, *p_x1b;
    __nv_bfloat16 *p_wq, *p_wp, *p_wc, *p_w1, *p_w2, *p_wc3;
    cudaGetSymbolAddress((void**)&p_x1,   g_x1);
    cudaGetSymbolAddress((void**)&p_conv, g_conv);
    cudaGetSymbolAddress((void**)&p_x2,   g_x2);
    cudaGetSymbolAddress((void**)&p_part, g_part);
    cudaGetSymbolAddress((void**)&p_stats,g_stats);
    cudaGetSymbolAddress((void**)&p_qkvb, g_qkvb);
    cudaGetSymbolAddress((void**)&p_xnb,  g_xnb);
    cudaGetSymbolAddress((void**)&p_attb, g_attb);
    cudaGetSymbolAddress((void**)&p_x1b,  g_x1b);
    cudaGetSymbolAddress((void**)&p_wq,   g_wq);
    cudaGetSymbolAddress((void**)&p_wp,   g_wp);
    cudaGetSymbolAddress((void**)&p_wc,   g_wc);
    cudaGetSymbolAddress((void**)&p_w1,   g_w1);
    cudaGetSymbolAddress((void**)&p_w2,   g_w2);
    cudaGetSymbolAddress((void**)&p_wc3,  g_wc3);

    const int CONV_SMEM = 32 * WP3 * 2 + 3 * 4000 * 2;   // 79808
    const int FC_SMEM   = 26624 + 19968 + 128 * 392 * 2; // 146944
    cudaFuncSetAttribute(conv3t_kernel, cudaFuncAttributeMaxDynamicSharedMemorySize, CONV_SMEM);
    cudaFuncSetAttribute(fc12_kernel,   cudaFuncAttributeMaxDynamicSharedMemorySize, FC_SMEM);

    // weight conversions (bf16)
    f2bf_kernel<<<(288*96+255)/256, 256>>>(qkv_w,   p_wq, 288*96);
    f2bf_kernel<<<(96*96+255)/256,  256>>>(proj_w,  p_wp, 96*96);
    f2bf_kernel<<<(96*96+255)/256,  256>>>(convp_w, p_wc, 96*96);
    f2bf_kernel<<<(384*96+255)/256, 256>>>(fc1_w,   p_w1, 384*96);
    f2bf_kernel<<<(96*384+255)/256, 256>>>(fc2_w,   p_w2, 96*384);
    wc3prep_kernel<<<(96*864+255)/256, 256>>>(conv3_w, p_wc3);

    // 1) LN1 -> bf16
    ln_bf_kernel<<<25088, 256>>>(x, n1w, n1b, p_xnb);
    // 2) qkv = xn @ qkv_w^T -> bf16
    tgemm<96,4><<<dim3(1568, 3), 256>>>(p_xnb, p_wq, nullptr, nullptr, p_qkvb, nullptr, 288);
    // 3) attention (bf16 in/out)
    attn_kernel<<<dim3(2048, 3), 224>>>(p_qkvb, p_attb);
    // 4) x1 = x + attn @ proj_w^T + proj_b  (fp32 + bf16 copy)
    tgemm<96,3><<<dim3(1568, 1), 256>>>(p_attb, p_wp, proj_b, x, p_x1, p_x1b, 96);
    // 5) grouped conv (tensor cores, rolling depth)
    conv3t_kernel<<<1176, 128, CONV_SMEM>>>(p_x1b, p_wc3, p_conv);
    // 6) GN stats
    gnred_kernel<<<1792, 256>>>(p_conv, p_part);
    gncomb_kernel<<<1, 16>>>(p_part, p_stats);
    // 7) fused: x2 = x1 + relu(GN(conv)) @ convp^T ; xnb = LN2(x2)
    convp_kernel<<<1568, 256>>>(p_conv, p_wc, p_stats, gn_w, gn_b, p_x1, n2w, n2b, p_x2, p_xnb);
    // 8) fused MLP: out = x2 + gelu(xn2 @ fc1^T + b1) @ fc2^T + b2
    fc12_kernel<<<1568, 256, FC_SMEM>>>(p_xnb, p_w1, p_w2, fc1_b, fc2_b, p_x2, out);
}

// round 7
// speedup vs baseline: 6.0081x; 1.1794x over previous
#include <cuda_runtime.h>
#include <cuda_bf16.h>
#include <math.h>
#include <cstdint>

// ---------------- problem constants ----------------
#define NTOK 200704           // 4*16*56*56

// ---------------- scratch (static device globals; allowed) ----------------
__device__ float g_x1  [NTOK*96];
__device__ float g_conv[NTOK*96];
__device__ float g_x2  [NTOK*96];
__device__ float g_part[4*4*112*2];
__device__ float g_stats[16*2];
__device__ __nv_bfloat16 g_qkvb[NTOK*288];
__device__ __nv_bfloat16 g_xnb [NTOK*96];
__device__ __nv_bfloat16 g_attb[NTOK*96];
__device__ __nv_bfloat16 g_x1b [NTOK*96];
__device__ __nv_bfloat16 g_wq  [288*96];
__device__ __nv_bfloat16 g_wp  [96*96];
__device__ __nv_bfloat16 g_wc  [96*96];
__device__ __nv_bfloat16 g_w1  [384*96];
__device__ __nv_bfloat16 g_w2  [96*384];
__device__ __nv_bfloat16 g_wc3 [96*864];   // conv weights, [co][tap*32+ci]

// ---------------- warp-MMA helpers (arch-agnostic PTX, sm_80+) --------------
__device__ __forceinline__ uint32_t smem_u32(const void* p) {
    uint32_t a;
    asm("{ .reg .u64 t; cvta.to.shared.u64 t, %1; cvt.u32.u64 %0, t; }" : "=r"(a) : "l"(p));
    return a;
}
__device__ __forceinline__ void ldsm_x4(uint32_t* r, uint32_t addr) {
    asm volatile("ldmatrix.sync.aligned.m8n8.x4.shared.b16 {%0,%1,%2,%3}, [%4];"
        : "=r"(r[0]), "=r"(r[1]), "=r"(r[2]), "=r"(r[3]) : "r"(addr));
}
__device__ __forceinline__ void mma16816(float* d, const uint32_t* a, const uint32_t* b) {
    asm volatile(
        "mma.sync.aligned.m16n8k16.row.col.f32.bf16.bf16.f32 "
        "{%0,%1,%2,%3}, {%4,%5,%6,%7}, {%8,%9}, {%0,%1,%2,%3};"
        : "+f"(d[0]), "+f"(d[1]), "+f"(d[2]), "+f"(d[3])
        : "r"(a[0]), "r"(a[1]), "r"(a[2]), "r"(a[3]), "r"(b[0]), "r"(b[1]));
}
__device__ __forceinline__ float gelu_exact(float v) {
    return 0.5f * v * (1.f + erff(v * 0.70710678118654752f));
}

// ---------------- tensor-core GEMM (K=96): out = epi( A @ W^T ) -------------
// CTA tile 128 x (96*NCH); A staged once, N chunks of 96 looped in-CTA.
// EPI: 3 = +bias+resid fp32 AND bf16 copy; 4 = bf16 store.
template<int NCH, int EPI>
__global__ __launch_bounds__(256)
void tgemm(const __nv_bfloat16* __restrict__ A, const __nv_bfloat16* __restrict__ W,
           const float* __restrict__ bias, const float* __restrict__ resid,
           void* __restrict__ outv, __nv_bfloat16* __restrict__ out2) {
    constexpr int PITCH = 104;
    constexpr int NOtot = 96 * NCH;
    __shared__ __nv_bfloat16 As[128 * PITCH];
    __shared__ __nv_bfloat16 Bs[96 * PITCH];
    const int tid = threadIdx.x;
    const int wid = tid >> 5, lane = tid & 31;
    const int warpM = wid & 3, warpN = wid >> 2;
    const long row0 = (long)blockIdx.x * 128;

    // stage A once
    #pragma unroll
    for (int it = 0; it < 6; it++) {
        int idx = tid + it * 256;
        int r = idx / 12, k = (idx % 12) * 8;
        uint4 v = *(const uint4*)(A + (row0 + r) * 96 + k);
        *(uint4*)(&As[r * PITCH + k]) = v;
    }

    const uint32_t smA = smem_u32(As), smB = smem_u32(Bs);
    const int t8 = lane & 7, tq = lane >> 3;
    const int rowA_base = warpM * 32 + t8 + (tq & 1) * 8;
    const int koffA = (tq >> 1) * 8;
    uint32_t offA[2];
    #pragma unroll
    for (int mf = 0; mf < 2; mf++)
        offA[mf] = smA + (uint32_t)(((rowA_base + mf * 16) * PITCH + koffA) * 2);
    const int rowB_base = warpN * 48 + t8 + (tq >> 1) * 8;
    const int koffB = (tq & 1) * 8;
    uint32_t offB[3];
    #pragma unroll
    for (int np = 0; np < 3; np++)
        offB[np] = smB + (uint32_t)(((rowB_base + np * 16) * PITCH + koffB) * 2);
    const int g = lane >> 2, tig = lane & 3;

    #pragma unroll
    for (int nc = 0; nc < NCH; nc++) {
        const int col0 = nc * 96;
        if (nc) __syncthreads();     // prior chunk's ldsm of Bs done
        for (int idx = tid; idx < 96 * 12; idx += 256) {
            int n = idx / 12, k = (idx % 12) * 8;
            uint4 v = *(const uint4*)(W + (long)(col0 + n) * 96 + k);
            *(uint4*)(&Bs[n * PITCH + k]) = v;
        }
        __syncthreads();

        float acc[2][6][4];
        #pragma unroll
        for (int i = 0; i < 2; i++)
            #pragma unroll
            for (int j = 0; j < 6; j++)
                #pragma unroll
                for (int q = 0; q < 4; q++) acc[i][j][q] = 0.f;
        #pragma unroll
        for (int ks = 0; ks < 6; ks++) {
            uint32_t af[2][4], bf[3][4];
            ldsm_x4(af[0], offA[0] + ks * 32);
            ldsm_x4(af[1], offA[1] + ks * 32);
            ldsm_x4(bf[0], offB[0] + ks * 32);
            ldsm_x4(bf[1], offB[1] + ks * 32);
            ldsm_x4(bf[2], offB[2] + ks * 32);
            #pragma unroll
            for (int mf = 0; mf < 2; mf++)
                #pragma unroll
                for (int np = 0; np < 3; np++) {
                    mma16816(acc[mf][np * 2 + 0], af[mf], &bf[np][0]);
                    mma16816(acc[mf][np * 2 + 1], af[mf], &bf[np][2]);
                }
        }

        #pragma unroll
        for (int mf = 0; mf < 2; mf++) {
            #pragma unroll
            for (int nf = 0; nf < 6; nf++) {
                int col = col0 + warpN * 48 + nf * 8 + tig * 2;
                #pragma unroll
                for (int h = 0; h < 2; h++) {
                    long row = row0 + warpM * 32 + mf * 16 + g + h * 8;
                    float v0 = acc[mf][nf][h * 2 + 0];
                    float v1 = acc[mf][nf][h * 2 + 1];
                    if (EPI == 3) {
                        if (bias) { v0 += bias[col]; v1 += bias[col + 1]; }
                        const float2 rr = *(const float2*)(resid + row * NOtot + col);
                        v0 += rr.x; v1 += rr.y;
                        *(float2*)((float*)outv + row * NOtot + col) = make_float2(v0, v1);
                        *(__nv_bfloat162*)(out2 + row * NOtot + col) = __floats2bfloat162_rn(v0, v1);
                    } else {
                        *(__nv_bfloat162*)((__nv_bfloat16*)outv + row * NOtot + col) = __floats2bfloat162_rn(v0, v1);
                    }
                }
            }
        }
    }
}

// ---------------- fused 1x1-conv GEMM: GN+ReLU prologue, LN2 epilogue -------
__global__ __launch_bounds__(256)
void convp_kernel(const float* __restrict__ conv, const __nv_bfloat16* __restrict__ W,
                  const float* __restrict__ stats, const float* __restrict__ gnw,
                  const float* __restrict__ gnb, const float* __restrict__ x1,
                  const float* __restrict__ n2w, const float* __restrict__ n2b,
                  float* __restrict__ x2, __nv_bfloat16* __restrict__ xnb) {
    constexpr int PITCH = 104;
    __shared__ __nv_bfloat16 As[128 * PITCH];
    __shared__ __nv_bfloat16 Bs[96 * PITCH];
    __shared__ float redS[128][2], redQ[128][2];
    const int tid = threadIdx.x;
    const int wid = tid >> 5, lane = tid & 31;
    const int warpM = wid & 3, warpN = wid >> 2;
    const long row0 = (long)blockIdx.x * 128;

    const int bidx = (int)(row0 / 50176) * 4;
    for (int idx = tid; idx < 128 * 24; idx += 256) {
        int r = idx / 24, k4 = (idx % 24) * 4;
        const float4 cv = *(const float4*)(conv + (row0 + r) * 96 + k4);
        int gi = bidx + k4 / 24;
        float mu = stats[gi * 2], rs = stats[gi * 2 + 1];
        float f0 = fmaxf((cv.x - mu) * rs * gnw[k4]     + gnb[k4],     0.f);
        float f1 = fmaxf((cv.y - mu) * rs * gnw[k4 + 1] + gnb[k4 + 1], 0.f);
        float f2 = fmaxf((cv.z - mu) * rs * gnw[k4 + 2] + gnb[k4 + 2], 0.f);
        float f3 = fmaxf((cv.w - mu) * rs * gnw[k4 + 3] + gnb[k4 + 3], 0.f);
        *(__nv_bfloat162*)(&As[r * PITCH + k4])     = __floats2bfloat162_rn(f0, f1);
        *(__nv_bfloat162*)(&As[r * PITCH + k4 + 2]) = __floats2bfloat162_rn(f2, f3);
    }
    for (int idx = tid; idx < 96 * 12; idx += 256) {
        int n = idx / 12, k = (idx % 12) * 8;
        uint4 v = *(const uint4*)(W + n * 96 + k);
        *(uint4*)(&Bs[n * PITCH + k]) = v;
    }
    __syncthreads();

    float acc[2][6][4];
    #pragma unroll
    for (int i = 0; i < 2; i++)
        #pragma unroll
        for (int j = 0; j < 6; j++)
            #pragma unroll
            for (int q = 0; q < 4; q++) acc[i][j][q] = 0.f;

    const uint32_t smA = smem_u32(As), smB = smem_u32(Bs);
    const int t8 = lane & 7, tq = lane >> 3;
    const int rowA_base = warpM * 32 + t8 + (tq & 1) * 8;
    const int koffA = (tq >> 1) * 8;
    uint32_t offA[2];
    #pragma unroll
    for (int mf = 0; mf < 2; mf++)
        offA[mf] = smA + (uint32_t)(((rowA_base + mf * 16) * PITCH + koffA) * 2);
    const int rowB_base = warpN * 48 + t8 + (tq >> 1) * 8;
    const int koffB = (tq & 1) * 8;
    uint32_t offB[3];
    #pragma unroll
    for (int np = 0; np < 3; np++)
        offB[np] = smB + (uint32_t)(((rowB_base + np * 16) * PITCH + koffB) * 2);

    #pragma unroll
    for (int ks = 0; ks < 6; ks++) {
        uint32_t af[2][4], bf[3][4];
        ldsm_x4(af[0], offA[0] + ks * 32);
        ldsm_x4(af[1], offA[1] + ks * 32);
        ldsm_x4(bf[0], offB[0] + ks * 32);
        ldsm_x4(bf[1], offB[1] + ks * 32);
        ldsm_x4(bf[2], offB[2] + ks * 32);
        #pragma unroll
        for (int mf = 0; mf < 2; mf++)
            #pragma unroll
            for (int np = 0; np < 3; np++) {
                mma16816(acc[mf][np * 2 + 0], af[mf], &bf[np][0]);
                mma16816(acc[mf][np * 2 + 1], af[mf], &bf[np][2]);
            }
    }

    const int g = lane >> 2, tig = lane & 3;
    #pragma unroll
    for (int mf = 0; mf < 2; mf++)
        #pragma unroll
        for (int h = 0; h < 2; h++) {
            int rl = warpM * 32 + mf * 16 + g + h * 8;
            long row = row0 + rl;
            float s = 0.f, q2 = 0.f;
            #pragma unroll
            for (int nf = 0; nf < 6; nf++) {
                int col = warpN * 48 + nf * 8 + tig * 2;
                const float2 rr = *(const float2*)(x1 + row * 96 + col);
                float v0 = acc[mf][nf][h * 2 + 0] + rr.x;
                float v1 = acc[mf][nf][h * 2 + 1] + rr.y;
                acc[mf][nf][h * 2 + 0] = v0;
                acc[mf][nf][h * 2 + 1] = v1;
                s += v0 + v1; q2 += v0 * v0 + v1 * v1;
            }
            s  += __shfl_xor_sync(0xFFFFFFFFu, s, 1);
            q2 += __shfl_xor_sync(0xFFFFFFFFu, q2, 1);
            s  += __shfl_xor_sync(0xFFFFFFFFu, s, 2);
            q2 += __shfl_xor_sync(0xFFFFFFFFu, q2, 2);
            if (tig == 0) { redS[rl][warpN] = s; redQ[rl][warpN] = q2; }
        }
    __syncthreads();

    #pragma unroll
    for (int mf = 0; mf < 2; mf++)
        #pragma unroll
        for (int h = 0; h < 2; h++) {
            int rl = warpM * 32 + mf * 16 + g + h * 8;
            long row = row0 + rl;
            float tot = redS[rl][0] + redS[rl][1];
            float tq2 = redQ[rl][0] + redQ[rl][1];
            float mu = tot * (1.f / 96.f);
            float var = tq2 * (1.f / 96.f) - mu * mu;
            float rs = rsqrtf(var + 1e-5f);
            #pragma unroll
            for (int nf = 0; nf < 6; nf++) {
                int col = warpN * 48 + nf * 8 + tig * 2;
                float v0 = acc[mf][nf][h * 2 + 0];
                float v1 = acc[mf][nf][h * 2 + 1];
                *(float2*)(x2 + row * 96 + col) = make_float2(v0, v1);
                float n0 = (v0 - mu) * rs * n2w[col]     + n2b[col];
                float n1 = (v1 - mu) * rs * n2w[col + 1] + n2b[col + 1];
                *(__nv_bfloat162*)(xnb + row * 96 + col) = __floats2bfloat162_rn(n0, n1);
            }
        }
}

// ---------------- fused MLP: out = x2 + gelu(xn@W1^T+b1) @ W2^T + b2 --------
// Interleaved hidden chunks through a 128x96 H buffer: 91KB smem, 2 CTAs/SM.
__global__ __launch_bounds__(256, 2)
void fc12_kernel(const __nv_bfloat16* __restrict__ xnb, const __nv_bfloat16* __restrict__ w1,
                 const __nv_bfloat16* __restrict__ w2, const float* __restrict__ b1,
                 const float* __restrict__ b2, const float* __restrict__ x2,
                 float* __restrict__ out) {
    constexpr int PITCH = 104;
    extern __shared__ char sm[];
    __nv_bfloat16* As  = (__nv_bfloat16*)sm;                       // 128*104 = 26624B
    __nv_bfloat16* Bs1 = (__nv_bfloat16*)(sm + 26624);             // 96*104  = 19968B
    __nv_bfloat16* Bs2 = (__nv_bfloat16*)(sm + 46592);             // 96*104
    __nv_bfloat16* Hs  = (__nv_bfloat16*)(sm + 66560);             // 128*104
    const int tid = threadIdx.x;
    const int wid = tid >> 5, lane = tid & 31;
    const int warpM = wid & 3, warpN = wid >> 2;
    const long row0 = (long)blockIdx.x * 128;

    #pragma unroll
    for (int it = 0; it < 6; it++) {
        int idx = tid + it * 256;
        int r = idx / 12, k = (idx % 12) * 8;
        uint4 v = *(const uint4*)(xnb + (row0 + r) * 96 + k);
        *(uint4*)(&As[r * PITCH + k]) = v;
    }

    const uint32_t smA = smem_u32(As), smB1 = smem_u32(Bs1), smB2 = smem_u32(Bs2), smH = smem_u32(Hs);
    const int t8 = lane & 7, tq = lane >> 3;
    const int rowA_base = warpM * 32 + t8 + (tq & 1) * 8;
    const int koffA = (tq >> 1) * 8;
    uint32_t offA[2], offH[2];
    #pragma unroll
    for (int mf = 0; mf < 2; mf++) {
        offA[mf] = smA + (uint32_t)(((rowA_base + mf * 16) * PITCH + koffA) * 2);
        offH[mf] = smH + (uint32_t)(((rowA_base + mf * 16) * PITCH + koffA) * 2);
    }
    const int rowB_base = warpN * 48 + t8 + (tq >> 1) * 8;
    const int koffB = (tq & 1) * 8;
    uint32_t offB1[3], offB2[3];
    #pragma unroll
    for (int np = 0; np < 3; np++) {
        offB1[np] = smB1 + (uint32_t)(((rowB_base + np * 16) * PITCH + koffB) * 2);
        offB2[np] = smB2 + (uint32_t)(((rowB_base + np * 16) * PITCH + koffB) * 2);
    }
    const int g = lane >> 2, tig = lane & 3;

    float acc2[2][6][4];
    #pragma unroll
    for (int i = 0; i < 2; i++)
        #pragma unroll
        for (int j = 0; j < 6; j++)
            #pragma unroll
            for (int q = 0; q < 4; q++) acc2[i][j][q] = 0.f;

    for (int nc = 0; nc < 4; nc++) {
        __syncthreads();    // prior chunk's Hs/Bs2 readers done (and As stores at nc=0 — sealed below)
        for (int idx = tid; idx < 96 * 12; idx += 256) {
            int n = idx / 12, k = (idx % 12) * 8;
            uint4 v1 = *(const uint4*)(w1 + (long)(nc * 96 + n) * 96 + k);
            *(uint4*)(&Bs1[n * PITCH + k]) = v1;
            uint4 v2 = *(const uint4*)(w2 + (long)n * 384 + nc * 96 + k);
            *(uint4*)(&Bs2[n * PITCH + k]) = v2;
        }
        __syncthreads();    // Bs1/Bs2 (+As) visible

        float acc1[2][6][4];
        #pragma unroll
        for (int i = 0; i < 2; i++)
            #pragma unroll
            for (int j = 0; j < 6; j++)
                #pragma unroll
                for (int q = 0; q < 4; q++) acc1[i][j][q] = 0.f;
        #pragma unroll
        for (int ks = 0; ks < 6; ks++) {
            uint32_t af[2][4], bf[3][4];
            ldsm_x4(af[0], offA[0] + ks * 32);
            ldsm_x4(af[1], offA[1] + ks * 32);
            ldsm_x4(bf[0], offB1[0] + ks * 32);
            ldsm_x4(bf[1], offB1[1] + ks * 32);
            ldsm_x4(bf[2], offB1[2] + ks * 32);
            #pragma unroll
            for (int mf = 0; mf < 2; mf++)
                #pragma unroll
                for (int np = 0; np < 3; np++) {
                    mma16816(acc1[mf][np * 2 + 0], af[mf], &bf[np][0]);
                    mma16816(acc1[mf][np * 2 + 1], af[mf], &bf[np][2]);
                }
        }
        // gelu epilogue -> Hs (chunk-local columns)
        #pragma unroll
        for (int mf = 0; mf < 2; mf++)
            #pragma unroll
            for (int nf = 0; nf < 6; nf++) {
                int hcol = warpN * 48 + nf * 8 + tig * 2;
                float bb0 = b1[nc * 96 + hcol], bb1 = b1[nc * 96 + hcol + 1];
                #pragma unroll
                for (int h = 0; h < 2; h++) {
                    int rl = warpM * 32 + mf * 16 + g + h * 8;
                    float v0 = gelu_exact(acc1[mf][nf][h * 2 + 0] + bb0);
                    float v1 = gelu_exact(acc1[mf][nf][h * 2 + 1] + bb1);
                    *(__nv_bfloat162*)(&Hs[rl * PITCH + hcol]) = __floats2bfloat162_rn(v0, v1);
                }
            }
        __syncthreads();    // Hs visible

        #pragma unroll
        for (int ks = 0; ks < 6; ks++) {
            uint32_t af[2][4], bf[3][4];
            ldsm_x4(af[0], offH[0] + ks * 32);
            ldsm_x4(af[1], offH[1] + ks * 32);
            ldsm_x4(bf[0], offB2[0] + ks * 32);
            ldsm_x4(bf[1], offB2[1] + ks * 32);
            ldsm_x4(bf[2], offB2[2] + ks * 32);
            #pragma unroll
            for (int mf = 0; mf < 2; mf++)
                #pragma unroll
                for (int np = 0; np < 3; np++) {
                    mma16816(acc2[mf][np * 2 + 0], af[mf], &bf[np][0]);
                    mma16816(acc2[mf][np * 2 + 1], af[mf], &bf[np][2]);
                }
        }
    }

    #pragma unroll
    for (int mf = 0; mf < 2; mf++)
        #pragma unroll
        for (int nf = 0; nf < 6; nf++) {
            int col = warpN * 48 + nf * 8 + tig * 2;
            #pragma unroll
            for (int h = 0; h < 2; h++) {
                long row = row0 + warpM * 32 + mf * 16 + g + h * 8;
                const float2 rr = *(const float2*)(x2 + row * 96 + col);
                float v0 = acc2[mf][nf][h * 2 + 0] + b2[col]     + rr.x;
                float v1 = acc2[mf][nf][h * 2 + 1] + b2[col + 1] + rr.y;
                *(float2*)(out + row * 96 + col) = make_float2(v0, v1);
            }
        }
}

// ---------------- tensor-core grouped 3x3x3 conv, rolling depth planes ------
#define CVP 40
#define WP3 872
__global__ __launch_bounds__(128)
void conv3t_kernel(const __nv_bfloat16* __restrict__ x, const __nv_bfloat16* __restrict__ wc3,
                   float* __restrict__ o) {
    extern __shared__ char smc[];
    __nv_bfloat16* ws   = (__nv_bfloat16*)smc;
    __nv_bfloat16* in_s = (__nv_bfloat16*)(smc + 32 * WP3 * 2);
    int bid = blockIdx.x;
    int g = bid % 3; int t = bid / 3;
    int tw = t % 7, th = (t / 7) % 7, dh = (t / 49) % 2, b = t / 98;
    int h0 = th * 8, w0 = tw * 8, d0 = dh * 8;
    int tid = threadIdx.x, wrp = tid >> 5, lane = tid & 31;

    for (int idx = tid; idx < 32 * 108; idx += 128) {
        int row = idx / 108, kc = (idx % 108) * 8;
        uint4 v = *(const uint4*)(wc3 + (g * 32 + row) * 864 + kc);
        *(uint4*)(ws + row * WP3 + kc) = v;
    }

    auto load_plane = [&](int dde, int slot) {
        for (int idx = tid; idx < 400; idx += 128) {
            int pos = idx >> 2, c8 = (idx & 3) * 8;
            int hh = pos / 10, ww2 = pos % 10;
            int ih = h0 - 1 + hh, iw = w0 - 1 + ww2;
            uint4 v = make_uint4(0, 0, 0, 0);
            if (dde >= 0 && dde < 16 && ih >= 0 && ih < 56 && iw >= 0 && iw < 56)
                v = *(const uint4*)(x + ((long)((b * 16 + dde) * 56 + ih) * 56 + iw) * 96 + g * 32 + c8);
            *(uint4*)(in_s + slot * 4000 + (hh * 10 + ww2) * CVP + c8) = v;
        }
    };
    load_plane(d0 - 1, (d0 + 2) % 3);
    load_plane(d0,      d0 % 3);

    const int t8 = lane & 7, tq = lane >> 3;
    const int mrow = t8 + (tq & 1) * 8;
    const int p = wrp * 16 + mrow;
    const int hr = p >> 3, wc = p & 7;
    const int koffA = (tq >> 1) * 8;
    const uint32_t inb = smem_u32(in_s);
    const uint32_t aoff = inb + (uint32_t)(((hr * 10 + wc) * CVP + koffA) * 2);
    const int nr = t8 + (tq >> 1) * 8;
    const int koffB = (tq & 1) * 8;
    const uint32_t wsb = smem_u32(ws);
    const uint32_t boff0 = wsb + (uint32_t)((nr * WP3 + koffB) * 2);
    const uint32_t boff1 = wsb + (uint32_t)(((nr + 16) * WP3 + koffB) * 2);
    const int g2 = lane >> 2, tig = lane & 3;

    for (int dl = 0; dl < 8; dl++) {
        int dcur = d0 + dl;
        __syncthreads();
        load_plane(dcur + 1, (dcur + 1) % 3);
        __syncthreads();

        int slots[3] = { (dcur + 2) % 3, dcur % 3, (dcur + 1) % 3 };

        float acc[4][4];
        #pragma unroll
        for (int i = 0; i < 4; i++)
            #pragma unroll
            for (int q = 0; q < 4; q++) acc[i][q] = 0.f;

        #pragma unroll
        for (int kd = 0; kd < 3; kd++)
            #pragma unroll
            for (int kh = 0; kh < 3; kh++)
                #pragma unroll
                for (int kw = 0; kw < 3; kw++) {
                    uint32_t abase = aoff + (uint32_t)((slots[kd] * 4000 + (kh * 10 + kw) * CVP) * 2);
                    int tap = kd * 9 + kh * 3 + kw;
                    #pragma unroll
                    for (int s = 0; s < 2; s++) {
                        uint32_t af[4], b0[4], b1[4];
                        ldsm_x4(af, abase + s * 32);
                        ldsm_x4(b0, boff0 + (uint32_t)((tap * 32 + s * 16) * 2));
                        ldsm_x4(b1, boff1 + (uint32_t)((tap * 32 + s * 16) * 2));
                        mma16816(acc[0], af, &b0[0]);
                        mma16816(acc[1], af, &b0[2]);
                        mma16816(acc[2], af, &b1[0]);
                        mma16816(acc[3], af, &b1[2]);
                    }
                }

        #pragma unroll
        for (int hbit = 0; hbit < 2; hbit++) {
            long tok = ((long)(b * 16 + dcur) * 56 + (h0 + 2 * wrp + hbit)) * 56 + (w0 + g2);
            float* orow = o + tok * 96 + g * 32;
            #pragma unroll
            for (int nf = 0; nf < 4; nf++) {
                int co = nf * 8 + tig * 2;
                *(float2*)(orow + co) = make_float2(acc[nf][hbit * 2], acc[nf][hbit * 2 + 1]);
            }
        }
    }
}

// ---------------- merged weight prep (all conversions in one launch) --------
__global__ void prep_kernel(const float* __restrict__ qkv_w, const float* __restrict__ proj_w,
                            const float* __restrict__ convp_w, const float* __restrict__ fc1_w,
                            const float* __restrict__ fc2_w, const float* __restrict__ conv3_w,
                            __nv_bfloat16* wq, __nv_bfloat16* wp, __nv_bfloat16* wc,
                            __nv_bfloat16* w1, __nv_bfloat16* w2, __nv_bfloat16* wc3) {
    int i = blockIdx.x * 256 + threadIdx.x;
    if (i < 27648) { wq[i] = __float2bfloat16(qkv_w[i]); return; }
    i -= 27648;
    if (i < 9216)  { wp[i] = __float2bfloat16(proj_w[i]); return; }
    i -= 9216;
    if (i < 9216)  { wc[i] = __float2bfloat16(convp_w[i]); return; }
    i -= 9216;
    if (i < 36864) { w1[i] = __float2bfloat16(fc1_w[i]); return; }
    i -= 36864;
    if (i < 36864) { w2[i] = __float2bfloat16(fc2_w[i]); return; }
    i -= 36864;
    if (i < 82944) {
        int co = i / 864, r = i % 864;
        int tap = r >> 5, ci = r & 31;
        wc3[i] = __float2bfloat16(conv3_w[co * 864 + ci * 27 + tap]);
    }
}

// ---------------- LayerNorm over C=96 -> bf16 (1 warp / token) --------------
__global__ void ln_bf_kernel(const float* __restrict__ x, const float* __restrict__ w,
                             const float* __restrict__ b, __nv_bfloat16* __restrict__ o) {
    int wid = threadIdx.x >> 5, lane = threadIdx.x & 31;
    long tok = (long)blockIdx.x * 8 + wid;
    const float* xr = x + tok * 96;
    float v0 = xr[lane], v1 = xr[lane + 32], v2 = xr[lane + 64];
    float s  = v0 + v1 + v2;
    float sq = v0*v0 + v1*v1 + v2*v2;
    #pragma unroll
    for (int off = 16; off; off >>= 1) {
        s  += __shfl_xor_sync(0xFFFFFFFFu, s,  off);
        sq += __shfl_xor_sync(0xFFFFFFFFu, sq, off);
    }
    float mu  = s * (1.f / 96.f);
    float var = sq * (1.f / 96.f) - mu * mu;
    float rs  = rsqrtf(var + 1e-5f);
    __nv_bfloat16* orow = o + tok * 96;
    orow[lane]      = __float2bfloat16((v0 - mu) * rs * w[lane]      + b[lane]);
    orow[lane + 32] = __float2bfloat16((v1 - mu) * rs * w[lane + 32] + b[lane + 32]);
    orow[lane + 64] = __float2bfloat16((v2 - mu) * rs * w[lane + 64] + b[lane + 64]);
}

// ---------------- multi-dilate local attention (bf16 in/out, fp32 math) -----
__global__ void attn_kernel(const __nv_bfloat16* __restrict__ qkv, __nv_bfloat16* __restrict__ outb) {
    __shared__ int   toks[98];
    __shared__ float ks[98 * 32];
    __shared__ float vs[98 * 32];
    int win = blockIdx.x;
    int dil = blockIdx.y + 1;
    int choff = blockIdx.y * 32;
    int tid = threadIdx.x;
    if (tid < 98) {
        int b  = win >> 9;
        int dq = (win >> 6) & 7;
        int hq = (win >> 3) & 7;
        int wq = win & 7;
        int wd = tid / 49, rem = tid % 49;
        int wh = rem / 7, ww = rem % 7;
        int d = dq * 2 + wd, h = hq * 7 + wh, w = wq * 7 + ww;
        toks[tid] = ((b * 16 + d) * 56 + h) * 56 + w;
    }
    __syncthreads();
    for (int idx = tid; idx < 98 * 32; idx += 224) {
        int n = idx >> 5, c2 = idx & 31;
        long base = (long)toks[n] * 288 + choff + c2;
        ks[idx] = __bfloat162float(qkv[base + 96]);
        vs[idx] = __bfloat162float(qkv[base + 192]);
    }
    __syncthreads();
    if (tid < 196) {
        int n = tid >> 1, head = tid & 1;
        long qbase = (long)toks[n] * 288 + choff + head * 16;
        float q[16];
        #pragma unroll
        for (int c = 0; c < 16; c++) q[c] = __bfloat162float(qkv[qbase + c]);
        float lr[3]; int mm[3];
        #pragma unroll
        for (int j = 0; j < 3; j++) {
            int m = n + (j - 1) * dil;
            mm[j] = m;
            float s = 0.f;
            if (m >= 0 && m < 98) {
                const float* kr = &ks[m * 32 + head * 16];
                #pragma unroll
                for (int c = 0; c < 16; c++) s += q[c] * kr[c];
            }
            lr[j] = s * 0.25f;
        }
        float mx = fmaxf(0.f, fmaxf(lr[0], fmaxf(lr[1], lr[2])));
        float e[3];
        e[0] = expf(lr[0] - mx); e[1] = expf(lr[1] - mx); e[2] = expf(lr[2] - mx);
        float denom = 6.f * expf(-mx) + e[0] + e[1] + e[2];
        float o[16];
        #pragma unroll
        for (int c = 0; c < 16; c++) o[c] = 0.f;
        #pragma unroll
        for (int j = 0; j < 3; j++) {
            int m = mm[j];
            if (m >= 0 && m < 98) {
                float a = e[j] / denom;
                const float* vr = &vs[m * 32 + head * 16];
                #pragma unroll
                for (int c = 0; c < 16; c++) o[c] += a * vr[c];
            }
        }
        long obase = (long)toks[n] * 96 + choff + head * 16;
        #pragma unroll
        for (int c = 0; c < 8; c++)
            *(__nv_bfloat162*)(outb + obase + c * 2) = __floats2bfloat162_rn(o[c * 2], o[c * 2 + 1]);
    }
}

// ---------------- GroupNorm(4) stats: deterministic 2-stage reduction -------
__global__ void gnred_kernel(const float* __restrict__ cv, float* __restrict__ part) {
    __shared__ float ss[256], sqv[256];
    int bg = blockIdx.x / 112, chunk = blockIdx.x % 112;
    int b = bg >> 2, gg = bg & 3;
    long vox0 = (long)b * 50176 + chunk * 448;
    float s = 0.f, q2 = 0.f;
    for (int idx = threadIdx.x; idx < 448 * 24; idx += 256) {
        int v = idx / 24, c2 = idx % 24;
        float val = cv[(vox0 + v) * 96 + gg * 24 + c2];
        s += val; q2 += val * val;
    }
    ss[threadIdx.x] = s; sqv[threadIdx.x] = q2;
    __syncthreads();
    for (int off = 128; off; off >>= 1) {
        if (threadIdx.x < off) {
            ss[threadIdx.x]  += ss[threadIdx.x + off];
            sqv[threadIdx.x] += sqv[threadIdx.x + off];
        }
        __syncthreads();
    }
    if (threadIdx.x == 0) {
        part[blockIdx.x * 2]     = ss[0];
        part[blockIdx.x * 2 + 1] = sqv[0];
    }
}

__global__ void gncomb_kernel(const float* __restrict__ part, float* __restrict__ stats) {
    int t = threadIdx.x;
    if (t < 16) {
        double s = 0.0, q2 = 0.0;
        for (int i = 0; i < 112; i++) {
            s  += (double)part[(t * 112 + i) * 2];
            q2 += (double)part[(t * 112 + i) * 2 + 1];
        }
        double N = 24.0 * 50176.0;
        double mu  = s / N;
        double var = q2 / N - mu * mu;
        stats[t * 2]     = (float)mu;
        stats[t * 2 + 1] = (float)(1.0 / sqrt(var + 1e-5));
    }
}

// ---------------- driver -----------------------------------------------------
extern "C" void kernel_launch(void* const* d_in, const int* in_sizes, int n_in,
                              void* d_out, int out_size) {
    const float* x       = (const float*)d_in[0];
    const float* n1w     = (const float*)d_in[1];
    const float* n1b     = (const float*)d_in[2];
    const float* qkv_w   = (const float*)d_in[3];
    const float* proj_w  = (const float*)d_in[4];
    const float* proj_b  = (const float*)d_in[5];
    const float* conv3_w = (const float*)d_in[6];
    const float* gn_w    = (const float*)d_in[7];
    const float* gn_b    = (const float*)d_in[8];
    const float* convp_w = (const float*)d_in[9];
    const float* n2w     = (const float*)d_in[10];
    const float* n2b     = (const float*)d_in[11];
    const float* fc1_w   = (const float*)d_in[12];
    const float* fc1_b   = (const float*)d_in[13];
    const float* fc2_w   = (const float*)d_in[14];
    const float* fc2_b   = (const float*)d_in[15];
    float* out = (float*)d_out;

    float *p_x1, *p_conv, *p_x2, *p_part, *p_stats;
    __nv_bfloat16 *p_qkvb, *p_xnb, *p_attb, *p_x1b;
    __nv_bfloat16 *p_wq, *p_wp, *p_wc, *p_w1, *p_w2, *p_wc3;
    cudaGetSymbolAddress((void**)&p_x1,   g_x1);
    cudaGetSymbolAddress((void**)&p_conv, g_conv);
    cudaGetSymbolAddress((void**)&p_x2,   g_x2);
    cudaGetSymbolAddress((void**)&p_part, g_part);
    cudaGetSymbolAddress((void**)&p_stats,g_stats);
    cudaGetSymbolAddress((void**)&p_qkvb, g_qkvb);
    cudaGetSymbolAddress((void**)&p_xnb,  g_xnb);
    cudaGetSymbolAddress((void**)&p_attb, g_attb);
    cudaGetSymbolAddress((void**)&p_x1b,  g_x1b);
    cudaGetSymbolAddress((void**)&p_wq,   g_wq);
    cudaGetSymbolAddress((void**)&p_wp,   g_wp);
    cudaGetSymbolAddress((void**)&p_wc,   g_wc);
    cudaGetSymbolAddress((void**)&p_w1,   g_w1);
    cudaGetSymbolAddress((void**)&p_w2,   g_w2);
    cudaGetSymbolAddress((void**)&p_wc3,  g_wc3);

    const int CONV_SMEM = 32 * WP3 * 2 + 3 * 4000 * 2;   // 79808
    const int FC_SMEM   = 26624 + 19968 + 19968 + 26624; // 93184
    cudaFuncSetAttribute(conv3t_kernel, cudaFuncAttributeMaxDynamicSharedMemorySize, CONV_SMEM);
    cudaFuncSetAttribute(fc12_kernel,   cudaFuncAttributeMaxDynamicSharedMemorySize, FC_SMEM);

    // 0) merged weight prep  (202752 total elements)
    prep_kernel<<<(202752 + 255) / 256, 256>>>(qkv_w, proj_w, convp_w, fc1_w, fc2_w, conv3_w,
                                               p_wq, p_wp, p_wc, p_w1, p_w2, p_wc3);
    // 1) LN1 -> bf16
    ln_bf_kernel<<<25088, 256>>>(x, n1w, n1b, p_xnb);
    // 2) qkv = xn @ qkv_w^T -> bf16 (A staged once, 3 N-chunks in-CTA)
    tgemm<3,4><<<1568, 256>>>(p_xnb, p_wq, nullptr, nullptr, p_qkvb, nullptr);
    // 3) attention (bf16 in/out)
    attn_kernel<<<dim3(2048, 3), 224>>>(p_qkvb, p_attb);
    // 4) x1 = x + attn @ proj_w^T + proj_b  (fp32 + bf16 copy)
    tgemm<1,3><<<1568, 256>>>(p_attb, p_wp, proj_b, x, p_x1, p_x1b);
    // 5) grouped conv (tensor cores, rolling depth)
    conv3t_kernel<<<1176, 128, CONV_SMEM>>>(p_x1b, p_wc3, p_conv);
    // 6) GN stats
    gnred_kernel<<<1792, 256>>>(p_conv, p_part);
    gncomb_kernel<<<1, 16>>>(p_part, p_stats);
    // 7) fused: x2 = x1 + relu(GN(conv)) @ convp^T ; xnb = LN2(x2)
    convp_kernel<<<1568, 256>>>(p_conv, p_wc, p_stats, gn_w, gn_b, p_x1, n2w, n2b, p_x2, p_xnb);
    // 8) fused MLP: out = x2 + gelu(xn2 @ fc1^T + b1) @ fc2^T + b2
    fc12_kernel<<<1568, 256, FC_SMEM>>>(p_xnb, p_w1, p_w2, fc1_b, fc2_b, p_x2, out);
}

// round 9
// speedup vs baseline: 6.9552x; 1.1576x over previous
#include <cuda_runtime.h>
#include <cuda_bf16.h>
#include <math.h>
#include <cstdint>

// ---------------- problem constants ----------------
#define NTOK 200704           // 4*16*56*56

// ---------------- scratch (static device globals; allowed) ----------------
__device__ __align__(16) float g_x1  [NTOK*96];
__device__ __align__(16) float g_conv[NTOK*96];
__device__ __align__(16) float g_x2  [NTOK*96];
__device__ __align__(16) float g_part[4*4*112*2];
__device__ __align__(16) float g_stats[16*2];
__device__ __align__(16) __nv_bfloat16 g_qkvb[NTOK*288];
__device__ __align__(16) __nv_bfloat16 g_xnb [NTOK*96];
__device__ __align__(16) __nv_bfloat16 g_attb[NTOK*96];
__device__ __align__(16) __nv_bfloat16 g_x1b [NTOK*96];
__device__ __align__(16) __nv_bfloat16 g_wq  [288*96];
__device__ __align__(16) __nv_bfloat16 g_wp  [96*96];
__device__ __align__(16) __nv_bfloat16 g_wc  [96*96];
__device__ __align__(16) __nv_bfloat16 g_w1  [384*96];
__device__ __align__(16) __nv_bfloat16 g_w2  [96*384];
__device__ __align__(16) __nv_bfloat16 g_wc3 [96*864];

// ---------------- warp-MMA helpers ------------------------------------------
__device__ __forceinline__ uint32_t smem_u32(const void* p) {
    uint32_t a;
    asm("{ .reg .u64 t; cvta.to.shared.u64 t, %1; cvt.u32.u64 %0, t; }" : "=r"(a) : "l"(p));
    return a;
}
__device__ __forceinline__ void ldsm_x4(uint32_t* r, uint32_t addr) {
    asm volatile("ldmatrix.sync.aligned.m8n8.x4.shared.b16 {%0,%1,%2,%3}, [%4];"
        : "=r"(r[0]), "=r"(r[1]), "=r"(r[2]), "=r"(r[3]) : "r"(addr));
}
__device__ __forceinline__ void mma16816(float* d, const uint32_t* a, const uint32_t* b) {
    asm volatile(
        "mma.sync.aligned.m16n8k16.row.col.f32.bf16.bf16.f32 "
        "{%0,%1,%2,%3}, {%4,%5,%6,%7}, {%8,%9}, {%0,%1,%2,%3};"
        : "+f"(d[0]), "+f"(d[1]), "+f"(d[2]), "+f"(d[3])
        : "r"(a[0]), "r"(a[1]), "r"(a[2]), "r"(a[3]), "r"(b[0]), "r"(b[1]));
}
__device__ __forceinline__ float gelu_exact(float v) {
    return 0.5f * v * (1.f + erff(v * 0.70710678118654752f));
}

// ---------------- tensor-core GEMM (K=96): out = epi( A @ W^T ) -------------
// PROLOG 0: A bf16 row-major load. PROLOG 1: A fp32 + fused LayerNorm -> bf16.
// EPI: 3 = +bias+resid fp32 AND bf16 copy; 4 = bf16 store.
template<int NCH, int EPI, int PROLOG>
__global__ __launch_bounds__(256)
void tgemm(const void* __restrict__ Ax, const __nv_bfloat16* __restrict__ W,
           const float* __restrict__ bias, const float* __restrict__ resid,
           void* __restrict__ outv, __nv_bfloat16* __restrict__ out2,
           const float* __restrict__ lnw, const float* __restrict__ lnb) {
    constexpr int PITCH = 104;
    constexpr int NOtot = 96 * NCH;
    __shared__ __align__(16) __nv_bfloat16 As[128 * PITCH];
    __shared__ __align__(16) __nv_bfloat16 Bs[96 * PITCH];
    const int tid = threadIdx.x;
    const int wid = tid >> 5, lane = tid & 31;
    const int warpM = wid & 3, warpN = wid >> 2;
    const long row0 = (long)blockIdx.x * 128;

    if (PROLOG == 0) {
        const __nv_bfloat16* A = (const __nv_bfloat16*)Ax;
        #pragma unroll
        for (int it = 0; it < 6; it++) {
            int idx = tid + it * 256;
            int r = idx / 12, k = (idx % 12) * 8;
            uint4 v = *(const uint4*)(A + (row0 + r) * 96 + k);
            *(uint4*)(&As[r * PITCH + k]) = v;
        }
    } else {
        // fused LayerNorm: thread pair (2r,2r+1) owns row r halves
        const int r = tid >> 1, half = tid & 1;
        const float* xr = (const float*)Ax + (row0 + r) * 96 + half * 48;
        float vb[48];
        float s = 0.f, q2 = 0.f;
        #pragma unroll
        for (int i = 0; i < 12; i++) {
            float4 f = *(const float4*)(xr + i * 4);
            vb[i*4] = f.x; vb[i*4+1] = f.y; vb[i*4+2] = f.z; vb[i*4+3] = f.w;
            s  += f.x + f.y + f.z + f.w;
            q2 += f.x*f.x + f.y*f.y + f.z*f.z + f.w*f.w;
        }
        s  += __shfl_xor_sync(0xFFFFFFFFu, s, 1);
        q2 += __shfl_xor_sync(0xFFFFFFFFu, q2, 1);
        float mu = s * (1.f / 96.f);
        float var = q2 * (1.f / 96.f) - mu * mu;
        float rs = rsqrtf(var + 1e-5f);
        #pragma unroll
        for (int j = 0; j < 48; j += 2) {
            int c = half * 48 + j;
            float n0 = (vb[j]   - mu) * rs * lnw[c]     + lnb[c];
            float n1 = (vb[j+1] - mu) * rs * lnw[c + 1] + lnb[c + 1];
            *(__nv_bfloat162*)(&As[r * PITCH + c]) = __floats2bfloat162_rn(n0, n1);
        }
    }

    const uint32_t smA = smem_u32(As), smB = smem_u32(Bs);
    const int t8 = lane & 7, tq = lane >> 3;
    const int rowA_base = warpM * 32 + t8 + (tq & 1) * 8;
    const int koffA = (tq >> 1) * 8;
    uint32_t offA[2];
    #pragma unroll
    for (int mf = 0; mf < 2; mf++)
        offA[mf] = smA + (uint32_t)(((rowA_base + mf * 16) * PITCH + koffA) * 2);
    const int rowB_base = warpN * 48 + t8 + (tq >> 1) * 8;
    const int koffB = (tq & 1) * 8;
    uint32_t offB[3];
    #pragma unroll
    for (int np = 0; np < 3; np++)
        offB[np] = smB + (uint32_t)(((rowB_base + np * 16) * PITCH + koffB) * 2);
    const int g = lane >> 2, tig = lane & 3;

    #pragma unroll
    for (int nc = 0; nc < NCH; nc++) {
        const int col0 = nc * 96;
        if (nc) __syncthreads();
        for (int idx = tid; idx < 96 * 12; idx += 256) {
            int n = idx / 12, k = (idx % 12) * 8;
            uint4 v = *(const uint4*)(W + (long)(col0 + n) * 96 + k);
            *(uint4*)(&Bs[n * PITCH + k]) = v;
        }
        __syncthreads();

        float acc[2][6][4];
        #pragma unroll
        for (int i = 0; i < 2; i++)
            #pragma unroll
            for (int j = 0; j < 6; j++)
                #pragma unroll
                for (int q = 0; q < 4; q++) acc[i][j][q] = 0.f;
        #pragma unroll
        for (int ks = 0; ks < 6; ks++) {
            uint32_t af[2][4], bf[3][4];
            ldsm_x4(af[0], offA[0] + ks * 32);
            ldsm_x4(af[1], offA[1] + ks * 32);
            ldsm_x4(bf[0], offB[0] + ks * 32);
            ldsm_x4(bf[1], offB[1] + ks * 32);
            ldsm_x4(bf[2], offB[2] + ks * 32);
            #pragma unroll
            for (int mf = 0; mf < 2; mf++)
                #pragma unroll
                for (int np = 0; np < 3; np++) {
                    mma16816(acc[mf][np * 2 + 0], af[mf], &bf[np][0]);
                    mma16816(acc[mf][np * 2 + 1], af[mf], &bf[np][2]);
                }
        }

        #pragma unroll
        for (int mf = 0; mf < 2; mf++) {
            #pragma unroll
            for (int nf = 0; nf < 6; nf++) {
                int col = col0 + warpN * 48 + nf * 8 + tig * 2;
                #pragma unroll
                for (int h = 0; h < 2; h++) {
                    long row = row0 + warpM * 32 + mf * 16 + g + h * 8;
                    float v0 = acc[mf][nf][h * 2 + 0];
                    float v1 = acc[mf][nf][h * 2 + 1];
                    if (EPI == 3) {
                        if (bias) { v0 += bias[col]; v1 += bias[col + 1]; }
                        const float2 rr = *(const float2*)(resid + row * NOtot + col);
                        v0 += rr.x; v1 += rr.y;
                        *(float2*)((float*)outv + row * NOtot + col) = make_float2(v0, v1);
                        *(__nv_bfloat162*)(out2 + row * NOtot + col) = __floats2bfloat162_rn(v0, v1);
                    } else {
                        *(__nv_bfloat162*)((__nv_bfloat16*)outv + row * NOtot + col) = __floats2bfloat162_rn(v0, v1);
                    }
                }
            }
        }
    }
}

// ---------------- fused 1x1-conv GEMM: GN+ReLU prologue, LN2 epilogue -------
__global__ __launch_bounds__(256)
void convp_kernel(const float* __restrict__ conv, const __nv_bfloat16* __restrict__ W,
                  const float* __restrict__ stats, const float* __restrict__ gnw,
                  const float* __restrict__ gnb, const float* __restrict__ x1,
                  const float* __restrict__ n2w, const float* __restrict__ n2b,
                  float* __restrict__ x2, __nv_bfloat16* __restrict__ xnb) {
    constexpr int PITCH = 104;
    __shared__ __align__(16) __nv_bfloat16 As[128 * PITCH];
    __shared__ __align__(16) __nv_bfloat16 Bs[96 * PITCH];
    __shared__ float redS[128][2], redQ[128][2];
    const int tid = threadIdx.x;
    const int wid = tid >> 5, lane = tid & 31;
    const int warpM = wid & 3, warpN = wid >> 2;
    const long row0 = (long)blockIdx.x * 128;

    const int bidx = (int)(row0 / 50176) * 4;
    for (int idx = tid; idx < 128 * 24; idx += 256) {
        int r = idx / 24, k4 = (idx % 24) * 4;
        const float4 cv = *(const float4*)(conv + (row0 + r) * 96 + k4);
        int gi = bidx + k4 / 24;
        float mu = stats[gi * 2], rs = stats[gi * 2 + 1];
        float f0 = fmaxf((cv.x - mu) * rs * gnw[k4]     + gnb[k4],     0.f);
        float f1 = fmaxf((cv.y - mu) * rs * gnw[k4 + 1] + gnb[k4 + 1], 0.f);
        float f2 = fmaxf((cv.z - mu) * rs * gnw[k4 + 2] + gnb[k4 + 2], 0.f);
        float f3 = fmaxf((cv.w - mu) * rs * gnw[k4 + 3] + gnb[k4 + 3], 0.f);
        *(__nv_bfloat162*)(&As[r * PITCH + k4])     = __floats2bfloat162_rn(f0, f1);
        *(__nv_bfloat162*)(&As[r * PITCH + k4 + 2]) = __floats2bfloat162_rn(f2, f3);
    }
    for (int idx = tid; idx < 96 * 12; idx += 256) {
        int n = idx / 12, k = (idx % 12) * 8;
        uint4 v = *(const uint4*)(W + n * 96 + k);
        *(uint4*)(&Bs[n * PITCH + k]) = v;
    }
    __syncthreads();

    float acc[2][6][4];
    #pragma unroll
    for (int i = 0; i < 2; i++)
        #pragma unroll
        for (int j = 0; j < 6; j++)
            #pragma unroll
            for (int q = 0; q < 4; q++) acc[i][j][q] = 0.f;

    const uint32_t smA = smem_u32(As), smB = smem_u32(Bs);
    const int t8 = lane & 7, tq = lane >> 3;
    const int rowA_base = warpM * 32 + t8 + (tq & 1) * 8;
    const int koffA = (tq >> 1) * 8;
    uint32_t offA[2];
    #pragma unroll
    for (int mf = 0; mf < 2; mf++)
        offA[mf] = smA + (uint32_t)(((rowA_base + mf * 16) * PITCH + koffA) * 2);
    const int rowB_base = warpN * 48 + t8 + (tq >> 1) * 8;
    const int koffB = (tq & 1) * 8;
    uint32_t offB[3];
    #pragma unroll
    for (int np = 0; np < 3; np++)
        offB[np] = smB + (uint32_t)(((rowB_base + np * 16) * PITCH + koffB) * 2);

    #pragma unroll
    for (int ks = 0; ks < 6; ks++) {
        uint32_t af[2][4], bf[3][4];
        ldsm_x4(af[0], offA[0] + ks * 32);
        ldsm_x4(af[1], offA[1] + ks * 32);
        ldsm_x4(bf[0], offB[0] + ks * 32);
        ldsm_x4(bf[1], offB[1] + ks * 32);
        ldsm_x4(bf[2], offB[2] + ks * 32);
        #pragma unroll
        for (int mf = 0; mf < 2; mf++)
            #pragma unroll
            for (int np = 0; np < 3; np++) {
                mma16816(acc[mf][np * 2 + 0], af[mf], &bf[np][0]);
                mma16816(acc[mf][np * 2 + 1], af[mf], &bf[np][2]);
            }
    }

    const int g = lane >> 2, tig = lane & 3;
    #pragma unroll
    for (int mf = 0; mf < 2; mf++)
        #pragma unroll
        for (int h = 0; h < 2; h++) {
            int rl = warpM * 32 + mf * 16 + g + h * 8;
            long row = row0 + rl;
            float s = 0.f, q2 = 0.f;
            #pragma unroll
            for (int nf = 0; nf < 6; nf++) {
                int col = warpN * 48 + nf * 8 + tig * 2;
                const float2 rr = *(const float2*)(x1 + row * 96 + col);
                float v0 = acc[mf][nf][h * 2 + 0] + rr.x;
                float v1 = acc[mf][nf][h * 2 + 1] + rr.y;
                acc[mf][nf][h * 2 + 0] = v0;
                acc[mf][nf][h * 2 + 1] = v1;
                s += v0 + v1; q2 += v0 * v0 + v1 * v1;
            }
            s  += __shfl_xor_sync(0xFFFFFFFFu, s, 1);
            q2 += __shfl_xor_sync(0xFFFFFFFFu, q2, 1);
            s  += __shfl_xor_sync(0xFFFFFFFFu, s, 2);
            q2 += __shfl_xor_sync(0xFFFFFFFFu, q2, 2);
            if (tig == 0) { redS[rl][warpN] = s; redQ[rl][warpN] = q2; }
        }
    __syncthreads();

    #pragma unroll
    for (int mf = 0; mf < 2; mf++)
        #pragma unroll
        for (int h = 0; h < 2; h++) {
            int rl = warpM * 32 + mf * 16 + g + h * 8;
            long row = row0 + rl;
            float tot = redS[rl][0] + redS[rl][1];
            float tq2 = redQ[rl][0] + redQ[rl][1];
            float mu = tot * (1.f / 96.f);
            float var = tq2 * (1.f / 96.f) - mu * mu;
            float rs = rsqrtf(var + 1e-5f);
            #pragma unroll
            for (int nf = 0; nf < 6; nf++) {
                int col = warpN * 48 + nf * 8 + tig * 2;
                float v0 = acc[mf][nf][h * 2 + 0];
                float v1 = acc[mf][nf][h * 2 + 1];
                *(float2*)(x2 + row * 96 + col) = make_float2(v0, v1);
                float n0 = (v0 - mu) * rs * n2w[col]     + n2b[col];
                float n1 = (v1 - mu) * rs * n2w[col + 1] + n2b[col + 1];
                *(__nv_bfloat162*)(xnb + row * 96 + col) = __floats2bfloat162_rn(n0, n1);
            }
        }
}

// ---------------- fused MLP: out = x2 + gelu(xn@W1^T+b1) @ W2^T + b2 --------
__global__ __launch_bounds__(256, 2)
void fc12_kernel(const __nv_bfloat16* __restrict__ xnb, const __nv_bfloat16* __restrict__ w1,
                 const __nv_bfloat16* __restrict__ w2, const float* __restrict__ b1,
                 const float* __restrict__ b2, const float* __restrict__ x2,
                 float* __restrict__ out) {
    constexpr int PITCH = 104;
    extern __shared__ __align__(16) char sm[];
    __nv_bfloat16* As  = (__nv_bfloat16*)sm;
    __nv_bfloat16* Bs1 = (__nv_bfloat16*)(sm + 26624);
    __nv_bfloat16* Bs2 = (__nv_bfloat16*)(sm + 46592);
    __nv_bfloat16* Hs  = (__nv_bfloat16*)(sm + 66560);
    const int tid = threadIdx.x;
    const int wid = tid >> 5, lane = tid & 31;
    const int warpM = wid & 3, warpN = wid >> 2;
    const long row0 = (long)blockIdx.x * 128;

    #pragma unroll
    for (int it = 0; it < 6; it++) {
        int idx = tid + it * 256;
        int r = idx / 12, k = (idx % 12) * 8;
        uint4 v = *(const uint4*)(xnb + (row0 + r) * 96 + k);
        *(uint4*)(&As[r * PITCH + k]) = v;
    }

    const uint32_t smA = smem_u32(As), smB1 = smem_u32(Bs1), smB2 = smem_u32(Bs2), smH = smem_u32(Hs);
    const int t8 = lane & 7, tq = lane >> 3;
    const int rowA_base = warpM * 32 + t8 + (tq & 1) * 8;
    const int koffA = (tq >> 1) * 8;
    uint32_t offA[2], offH[2];
    #pragma unroll
    for (int mf = 0; mf < 2; mf++) {
        offA[mf] = smA + (uint32_t)(((rowA_base + mf * 16) * PITCH + koffA) * 2);
        offH[mf] = smH + (uint32_t)(((rowA_base + mf * 16) * PITCH + koffA) * 2);
    }
    const int rowB_base = warpN * 48 + t8 + (tq >> 1) * 8;
    const int koffB = (tq & 1) * 8;
    uint32_t offB1[3], offB2[3];
    #pragma unroll
    for (int np = 0; np < 3; np++) {
        offB1[np] = smB1 + (uint32_t)(((rowB_base + np * 16) * PITCH + koffB) * 2);
        offB2[np] = smB2 + (uint32_t)(((rowB_base + np * 16) * PITCH + koffB) * 2);
    }
    const int g = lane >> 2, tig = lane & 3;

    float acc2[2][6][4];
    #pragma unroll
    for (int i = 0; i < 2; i++)
        #pragma unroll
        for (int j = 0; j < 6; j++)
            #pragma unroll
            for (int q = 0; q < 4; q++) acc2[i][j][q] = 0.f;

    for (int nc = 0; nc < 4; nc++) {
        __syncthreads();
        for (int idx = tid; idx < 96 * 12; idx += 256) {
            int n = idx / 12, k = (idx % 12) * 8;
            uint4 v1 = *(const uint4*)(w1 + (long)(nc * 96 + n) * 96 + k);
            *(uint4*)(&Bs1[n * PITCH + k]) = v1;
            uint4 v2 = *(const uint4*)(w2 + (long)n * 384 + nc * 96 + k);
            *(uint4*)(&Bs2[n * PITCH + k]) = v2;
        }
        __syncthreads();

        float acc1[2][6][4];
        #pragma unroll
        for (int i = 0; i < 2; i++)
            #pragma unroll
            for (int j = 0; j < 6; j++)
                #pragma unroll
                for (int q = 0; q < 4; q++) acc1[i][j][q] = 0.f;
        #pragma unroll
        for (int ks = 0; ks < 6; ks++) {
            uint32_t af[2][4], bf[3][4];
            ldsm_x4(af[0], offA[0] + ks * 32);
            ldsm_x4(af[1], offA[1] + ks * 32);
            ldsm_x4(bf[0], offB1[0] + ks * 32);
            ldsm_x4(bf[1], offB1[1] + ks * 32);
            ldsm_x4(bf[2], offB1[2] + ks * 32);
            #pragma unroll
            for (int mf = 0; mf < 2; mf++)
                #pragma unroll
                for (int np = 0; np < 3; np++) {
                    mma16816(acc1[mf][np * 2 + 0], af[mf], &bf[np][0]);
                    mma16816(acc1[mf][np * 2 + 1], af[mf], &bf[np][2]);
                }
        }
        #pragma unroll
        for (int mf = 0; mf < 2; mf++)
            #pragma unroll
            for (int nf = 0; nf < 6; nf++) {
                int hcol = warpN * 48 + nf * 8 + tig * 2;
                float bb0 = b1[nc * 96 + hcol], bb1 = b1[nc * 96 + hcol + 1];
                #pragma unroll
                for (int h = 0; h < 2; h++) {
                    int rl = warpM * 32 + mf * 16 + g + h * 8;
                    float v0 = gelu_exact(acc1[mf][nf][h * 2 + 0] + bb0);
                    float v1 = gelu_exact(acc1[mf][nf][h * 2 + 1] + bb1);
                    *(__nv_bfloat162*)(&Hs[rl * PITCH + hcol]) = __floats2bfloat162_rn(v0, v1);
                }
            }
        __syncthreads();

        #pragma unroll
        for (int ks = 0; ks < 6; ks++) {
            uint32_t af[2][4], bf[3][4];
            ldsm_x4(af[0], offH[0] + ks * 32);
            ldsm_x4(af[1], offH[1] + ks * 32);
            ldsm_x4(bf[0], offB2[0] + ks * 32);
            ldsm_x4(bf[1], offB2[1] + ks * 32);
            ldsm_x4(bf[2], offB2[2] + ks * 32);
            #pragma unroll
            for (int mf = 0; mf < 2; mf++)
                #pragma unroll
                for (int np = 0; np < 3; np++) {
                    mma16816(acc2[mf][np * 2 + 0], af[mf], &bf[np][0]);
                    mma16816(acc2[mf][np * 2 + 1], af[mf], &bf[np][2]);
                }
        }
    }

    #pragma unroll
    for (int mf = 0; mf < 2; mf++)
        #pragma unroll
        for (int nf = 0; nf < 6; nf++) {
            int col = warpN * 48 + nf * 8 + tig * 2;
            #pragma unroll
            for (int h = 0; h < 2; h++) {
                long row = row0 + warpM * 32 + mf * 16 + g + h * 8;
                const float2 rr = *(const float2*)(x2 + row * 96 + col);
                float v0 = acc2[mf][nf][h * 2 + 0] + b2[col]     + rr.x;
                float v1 = acc2[mf][nf][h * 2 + 1] + b2[col + 1] + rr.y;
                *(float2*)(out + row * 96 + col) = make_float2(v0, v1);
            }
        }
}

// ---------------- tensor-core grouped 3x3x3 conv, rolling depth planes ------
#define CVP 40
#define WP3 872
__global__ __launch_bounds__(128)
void conv3t_kernel(const __nv_bfloat16* __restrict__ x, const __nv_bfloat16* __restrict__ wc3,
                   float* __restrict__ o) {
    extern __shared__ __align__(16) char smc[];
    __nv_bfloat16* ws   = (__nv_bfloat16*)smc;
    __nv_bfloat16* in_s = (__nv_bfloat16*)(smc + 32 * WP3 * 2);
    int bid = blockIdx.x;
    int g = bid % 3; int t = bid / 3;
    int tw = t % 7, th = (t / 7) % 7, dh = (t / 49) % 2, b = t / 98;
    int h0 = th * 8, w0 = tw * 8, d0 = dh * 8;
    int tid = threadIdx.x, wrp = tid >> 5, lane = tid & 31;

    for (int idx = tid; idx < 32 * 108; idx += 128) {
        int row = idx / 108, kc = (idx % 108) * 8;
        uint4 v = *(const uint4*)(wc3 + (g * 32 + row) * 864 + kc);
        *(uint4*)(ws + row * WP3 + kc) = v;
    }

    auto load_plane = [&](int dde, int slot) {
        for (int idx = tid; idx < 400; idx += 128) {
            int pos = idx >> 2, c8 = (idx & 3) * 8;
            int hh = pos / 10, ww2 = pos % 10;
            int ih = h0 - 1 + hh, iw = w0 - 1 + ww2;
            uint4 v = make_uint4(0, 0, 0, 0);
            if (dde >= 0 && dde < 16 && ih >= 0 && ih < 56 && iw >= 0 && iw < 56)
                v = *(const uint4*)(x + ((long)((b * 16 + dde) * 56 + ih) * 56 + iw) * 96 + g * 32 + c8);
            *(uint4*)(in_s + slot * 4000 + (hh * 10 + ww2) * CVP + c8) = v;
        }
    };
    load_plane(d0 - 1, (d0 + 2) % 3);
    load_plane(d0,      d0 % 3);

    const int t8 = lane & 7, tq = lane >> 3;
    const int mrow = t8 + (tq & 1) * 8;
    const int p = wrp * 16 + mrow;
    const int hr = p >> 3, wc = p & 7;
    const int koffA = (tq >> 1) * 8;
    const uint32_t inb = smem_u32(in_s);
    const uint32_t aoff = inb + (uint32_t)(((hr * 10 + wc) * CVP + koffA) * 2);
    const int nr = t8 + (tq >> 1) * 8;
    const int koffB = (tq & 1) * 8;
    const uint32_t wsb = smem_u32(ws);
    const uint32_t boff0 = wsb + (uint32_t)((nr * WP3 + koffB) * 2);
    const uint32_t boff1 = wsb + (uint32_t)(((nr + 16) * WP3 + koffB) * 2);
    const int g2 = lane >> 2, tig = lane & 3;

    for (int dl = 0; dl < 8; dl++) {
        int dcur = d0 + dl;
        __syncthreads();
        load_plane(dcur + 1, (dcur + 1) % 3);
        __syncthreads();

        int slots[3] = { (dcur + 2) % 3, dcur % 3, (dcur + 1) % 3 };

        float acc[4][4];
        #pragma unroll
        for (int i = 0; i < 4; i++)
            #pragma unroll
            for (int q = 0; q < 4; q++) acc[i][q] = 0.f;

        #pragma unroll
        for (int kd = 0; kd < 3; kd++)
            #pragma unroll
            for (int kh = 0; kh < 3; kh++)
                #pragma unroll
                for (int kw = 0; kw < 3; kw++) {
                    uint32_t abase = aoff + (uint32_t)((slots[kd] * 4000 + (kh * 10 + kw) * CVP) * 2);
                    int tap = kd * 9 + kh * 3 + kw;
                    #pragma unroll
                    for (int s = 0; s < 2; s++) {
                        uint32_t af[4], b0[4], b1[4];
                        ldsm_x4(af, abase + s * 32);
                        ldsm_x4(b0, boff0 + (uint32_t)((tap * 32 + s * 16) * 2));
                        ldsm_x4(b1, boff1 + (uint32_t)((tap * 32 + s * 16) * 2));
                        mma16816(acc[0], af, &b0[0]);
                        mma16816(acc[1], af, &b0[2]);
                        mma16816(acc[2], af, &b1[0]);
                        mma16816(acc[3], af, &b1[2]);
                    }
                }

        #pragma unroll
        for (int hbit = 0; hbit < 2; hbit++) {
            long tok = ((long)(b * 16 + dcur) * 56 + (h0 + 2 * wrp + hbit)) * 56 + (w0 + g2);
            float* orow = o + tok * 96 + g * 32;
            #pragma unroll
            for (int nf = 0; nf < 4; nf++) {
                int co = nf * 8 + tig * 2;
                *(float2*)(orow + co) = make_float2(acc[nf][hbit * 2], acc[nf][hbit * 2 + 1]);
            }
        }
    }
}

// ---------------- merged weight prep ----------------------------------------
__global__ void prep_kernel(const float* __restrict__ qkv_w, const float* __restrict__ proj_w,
                            const float* __restrict__ convp_w, const float* __restrict__ fc1_w,
                            const float* __restrict__ fc2_w, const float* __restrict__ conv3_w,
                            __nv_bfloat16* wq, __nv_bfloat16* wp, __nv_bfloat16* wc,
                            __nv_bfloat16* w1, __nv_bfloat16* w2, __nv_bfloat16* wc3) {
    int i = blockIdx.x * 256 + threadIdx.x;
    if (i < 27648) { wq[i] = __float2bfloat16(qkv_w[i]); return; }
    i -= 27648;
    if (i < 9216)  { wp[i] = __float2bfloat16(proj_w[i]); return; }
    i -= 9216;
    if (i < 9216)  { wc[i] = __float2bfloat16(convp_w[i]); return; }
    i -= 9216;
    if (i < 36864) { w1[i] = __float2bfloat16(fc1_w[i]); return; }
    i -= 36864;
    if (i < 36864) { w2[i] = __float2bfloat16(fc2_w[i]); return; }
    i -= 36864;
    if (i < 82944) {
        int co = i / 864, r = i % 864;
        int tap = r >> 5, ci = r & 31;
        wc3[i] = __float2bfloat16(conv3_w[co * 864 + ci * 27 + tap]);
    }
}

// ---------------- multi-dilate local attention (vectorized bf16) ------------
__global__ void attn_kernel(const __nv_bfloat16* __restrict__ qkv, __nv_bfloat16* __restrict__ outb) {
    __shared__ __align__(16) __nv_bfloat16 ks[98 * 32];
    __shared__ __align__(16) __nv_bfloat16 vs[98 * 32];
    __shared__ int toks[98];
    int win = blockIdx.x;
    int dil = blockIdx.y + 1;
    int choff = blockIdx.y * 32;
    int tid = threadIdx.x;
    if (tid < 98) {
        int b  = win >> 9;
        int dq = (win >> 6) & 7;
        int hq = (win >> 3) & 7;
        int wq = win & 7;
        int wd = tid / 49, rem = tid % 49;
        int wh = rem / 7, ww = rem % 7;
        int d = dq * 2 + wd, h = hq * 7 + wh, w = wq * 7 + ww;
        toks[tid] = ((b * 16 + d) * 56 + h) * 56 + w;
    }
    __syncthreads();
    // k/v staged as bf16 via uint4 (16B): 98 tokens x 4 chunks x {k,v}
    for (int idx = tid; idx < 98 * 8; idx += 224) {
        int n = idx >> 3, sub = idx & 7;
        int isv = sub >> 2, c8 = (sub & 3) * 8;
        long base = (long)toks[n] * 288 + choff + (isv ? 192 : 96) + c8;
        uint4 v = *(const uint4*)(qkv + base);
        *(uint4*)((isv ? vs : ks) + n * 32 + c8) = v;
    }
    __syncthreads();
    if (tid < 196) {
        int n = tid >> 1, head = tid & 1;
        long qbase = (long)toks[n] * 288 + choff + head * 16;
        float q[16];
        {
            uint4 qa = *(const uint4*)(qkv + qbase);
            uint4 qb = *(const uint4*)(qkv + qbase + 8);
            const __nv_bfloat162* qp = (const __nv_bfloat162*)&qa;
            #pragma unroll
            for (int i = 0; i < 4; i++) {
                float2 f = __bfloat1622float2(qp[i]);
                q[i * 2] = f.x; q[i * 2 + 1] = f.y;
            }
            qp = (const __nv_bfloat162*)&qb;
            #pragma unroll
            for (int i = 0; i < 4; i++) {
                float2 f = __bfloat1622float2(qp[i]);
                q[8 + i * 2] = f.x; q[8 + i * 2 + 1] = f.y;
            }
        }
        float lr[3]; int mm[3];
        #pragma unroll
        for (int j = 0; j < 3; j++) {
            int m = n + (j - 1) * dil;
            mm[j] = m;
            float s = 0.f;
            if (m >= 0 && m < 98) {
                const __nv_bfloat162* kr = (const __nv_bfloat162*)&ks[m * 32 + head * 16];
                #pragma unroll
                for (int c = 0; c < 8; c++) {
                    float2 f = __bfloat1622float2(kr[c]);
                    s += q[c * 2] * f.x + q[c * 2 + 1] * f.y;
                }
            }
            lr[j] = s * 0.25f;
        }
        float mx = fmaxf(0.f, fmaxf(lr[0], fmaxf(lr[1], lr[2])));
        float e[3];
        e[0] = expf(lr[0] - mx); e[1] = expf(lr[1] - mx); e[2] = expf(lr[2] - mx);
        float denom = 6.f * expf(-mx) + e[0] + e[1] + e[2];
        float o[16];
        #pragma unroll
        for (int c = 0; c < 16; c++) o[c] = 0.f;
        #pragma unroll
        for (int j = 0; j < 3; j++) {
            int m = mm[j];
            if (m >= 0 && m < 98) {
                float a = e[j] / denom;
                const __nv_bfloat162* vr = (const __nv_bfloat162*)&vs[m * 32 + head * 16];
                #pragma unroll
                for (int c = 0; c < 8; c++) {
                    float2 f = __bfloat1622float2(vr[c]);
                    o[c * 2]     += a * f.x;
                    o[c * 2 + 1] += a * f.y;
                }
            }
        }
        long obase = (long)toks[n] * 96 + choff + head * 16;
        #pragma unroll
        for (int c = 0; c < 8; c++)
            *(__nv_bfloat162*)(outb + obase + c * 2) = __floats2bfloat162_rn(o[c * 2], o[c * 2 + 1]);
    }
}

// ---------------- GroupNorm(4) stats: deterministic 2-stage reduction -------
__global__ void gnred_kernel(const float* __restrict__ cv, float* __restrict__ part) {
    __shared__ float ss[256], sqv[256];
    int bg = blockIdx.x / 112, chunk = blockIdx.x % 112;
    int b = bg >> 2, gg = bg & 3;
    long vox0 = (long)b * 50176 + chunk * 448;
    float s = 0.f, q2 = 0.f;
    for (int idx = threadIdx.x; idx < 448 * 24; idx += 256) {
        int v = idx / 24, c2 = idx % 24;
        float val = cv[(vox0 + v) * 96 + gg * 24 + c2];
        s += val; q2 += val * val;
    }
    ss[threadIdx.x] = s; sqv[threadIdx.x] = q2;
    __syncthreads();
    for (int off = 128; off; off >>= 1) {
        if (threadIdx.x < off) {
            ss[threadIdx.x]  += ss[threadIdx.x + off];
            sqv[threadIdx.x] += sqv[threadIdx.x + off];
        }
        __syncthreads();
    }
    if (threadIdx.x == 0) {
        part[blockIdx.x * 2]     = ss[0];
        part[blockIdx.x * 2 + 1] = sqv[0];
    }
}

__global__ void gncomb_kernel(const float* __restrict__ part, float* __restrict__ stats) {
    int t = threadIdx.x;
    if (t < 16) {
        double s = 0.0, q2 = 0.0;
        for (int i = 0; i < 112; i++) {
            s  += (double)part[(t * 112 + i) * 2];
            q2 += (double)part[(t * 112 + i) * 2 + 1];
        }
        double N = 24.0 * 50176.0;
        double mu  = s / N;
        double var = q2 / N - mu * mu;
        stats[t * 2]     = (float)mu;
        stats[t * 2 + 1] = (float)(1.0 / sqrt(var + 1e-5));
    }
}

// ---------------- driver -----------------------------------------------------
extern "C" void kernel_launch(void* const* d_in, const int* in_sizes, int n_in,
                              void* d_out, int out_size) {
    const float* x       = (const float*)d_in[0];
    const float* n1w     = (const float*)d_in[1];
    const float* n1b     = (const float*)d_in[2];
    const float* qkv_w   = (const float*)d_in[3];
    const float* proj_w  = (const float*)d_in[4];
    const float* proj_b  = (const float*)d_in[5];
    const float* conv3_w = (const float*)d_in[6];
    const float* gn_w    = (const float*)d_in[7];
    const float* gn_b    = (const float*)d_in[8];
    const float* convp_w = (const float*)d_in[9];
    const float* n2w     = (const float*)d_in[10];
    const float* n2b     = (const float*)d_in[11];
    const float* fc1_w   = (const float*)d_in[12];
    const float* fc1_b   = (const float*)d_in[13];
    const float* fc2_w   = (const float*)d_in[14];
    const float* fc2_b   = (const float*)d_in[15];
    float* out = (float*)d_out;

    float *p_x1, *p_conv, *p_x2, *p_part, *p_stats;
    __nv_bfloat16 *p_qkvb, *p_xnb, *p_attb, *p_x1b;
    __nv_bfloat16 *p_wq, *p_wp, *p_wc, *p_w1, *p_w2, *p_wc3;
    cudaGetSymbolAddress((void**)&p_x1,   g_x1);
    cudaGetSymbolAddress((void**)&p_conv, g_conv);
    cudaGetSymbolAddress((void**)&p_x2,   g_x2);
    cudaGetSymbolAddress((void**)&p_part, g_part);
    cudaGetSymbolAddress((void**)&p_stats,g_stats);
    cudaGetSymbolAddress((void**)&p_qkvb, g_qkvb);
    cudaGetSymbolAddress((void**)&p_xnb,  g_xnb);
    cudaGetSymbolAddress((void**)&p_attb, g_attb);
    cudaGetSymbolAddress((void**)&p_x1b,  g_x1b);
    cudaGetSymbolAddress((void**)&p_wq,   g_wq);
    cudaGetSymbolAddress((void**)&p_wp,   g_wp);
    cudaGetSymbolAddress((void**)&p_wc,   g_wc);
    cudaGetSymbolAddress((void**)&p_w1,   g_w1);
    cudaGetSymbolAddress((void**)&p_w2,   g_w2);
    cudaGetSymbolAddress((void**)&p_wc3,  g_wc3);

    const int CONV_SMEM = 32 * WP3 * 2 + 3 * 4000 * 2;
    const int FC_SMEM   = 26624 + 19968 + 19968 + 26624;
    cudaFuncSetAttribute(conv3t_kernel, cudaFuncAttributeMaxDynamicSharedMemorySize, CONV_SMEM);
    cudaFuncSetAttribute(fc12_kernel,   cudaFuncAttributeMaxDynamicSharedMemorySize, FC_SMEM);

    // 0) merged weight prep
    prep_kernel<<<(202752 + 255) / 256, 256>>>(qkv_w, proj_w, convp_w, fc1_w, fc2_w, conv3_w,
                                               p_wq, p_wp, p_wc, p_w1, p_w2, p_wc3);
    // 1) qkv = LN1(x) @ qkv_w^T -> bf16  (LN fused into prologue)
    tgemm<3,4,1><<<1568, 256>>>(x, p_wq, nullptr, nullptr, p_qkvb, nullptr, n1w, n1b);
    // 2) attention (vectorized bf16)
    attn_kernel<<<dim3(2048, 3), 224>>>(p_qkvb, p_attb);
    // 3) x1 = x + attn @ proj_w^T + proj_b  (fp32 + bf16 copy)
    tgemm<1,3,0><<<1568, 256>>>(p_attb, p_wp, proj_b, x, p_x1, p_x1b, nullptr, nullptr);
    // 4) grouped conv (tensor cores, rolling depth)
    conv3t_kernel<<<1176, 128, CONV_SMEM>>>(p_x1b, p_wc3, p_conv);
    // 5) GN stats
    gnred_kernel<<<1792, 256>>>(p_conv, p_part);
    gncomb_kernel<<<1, 16>>>(p_part, p_stats);
    // 6) fused: x2 = x1 + relu(GN(conv)) @ convp^T ; xnb = LN2(x2)
    convp_kernel<<<1568, 256>>>(p_conv, p_wc, p_stats, gn_w, gn_b, p_x1, n2w, n2b, p_x2, p_xnb);
    // 7) fused MLP
    fc12_kernel<<<1568, 256, FC_SMEM>>>(p_xnb, p_w1, p_w2, fc1_b, fc2_b, p_x2, out);
}